// round 5
// baseline (speedup 1.0000x reference)
#include <cuda_runtime.h>
#include <cstdint>

// ---------------- problem constants ----------------
#define B_      32
#define PP      49
#define NW      64
#define BNW     2048
#define MTOK    100352                 // BNW*49
#define QS      25690112               // BNW*8*49*32
#define OUT_ELEMS 25690112

#define NEG_INF __int_as_float(0xff800000)

// ---------------- scratch ----------------
__device__ float g_xw[(size_t)MTOK * 256];
__device__ float g_qkv[(size_t)3 * QS];
__device__ float g_otok[(size_t)MTOK * 256];
__device__ float g_mask[NW * PP * PP];

// ---------------- tf32 helpers ----------------
__device__ __forceinline__ unsigned f2tf(float f) {
    unsigned u; asm("cvt.rna.tf32.f32 %0, %1;" : "=r"(u) : "f"(f)); return u;
}
// D += A(16x8)*B(8x8) tf32, f32 accum. g=lane>>2, t=lane&3.
__device__ __forceinline__ void mma_tf32(float* c, const unsigned* a, const unsigned* b) {
    asm volatile("mma.sync.aligned.m16n8k8.row.col.f32.tf32.tf32.f32 "
        "{%0,%1,%2,%3}, {%4,%5,%6,%7}, {%8,%9}, {%0,%1,%2,%3};"
        : "+f"(c[0]), "+f"(c[1]), "+f"(c[2]), "+f"(c[3])
        : "r"(a[0]), "r"(a[1]), "r"(a[2]), "r"(a[3]), "r"(b[0]), "r"(b[1]));
}
__device__ __forceinline__ void barq(int id) {
    asm volatile("bar.sync %0, 128;" :: "r"(id) : "memory");
}

// ---------------- kernel 1: gather + roll(-3) + window permute ----------------
__global__ void gather_kernel(const float* __restrict__ x) {
    __shared__ float s[32 * 57];
    int xsrow = blockIdx.x;
    int c0 = blockIdx.y * 32;
    int b = blockIdx.z;
    int r = xsrow + 3; if (r >= 56) r -= 56;
    const float* xb = x + ((size_t)(b * 256 + c0) * 3136) + r * 56;
    for (int i = threadIdx.x; i < 32 * 56; i += blockDim.x) {
        int c = i / 56, col = i - c * 56;
        s[c * 57 + col] = xb[(size_t)c * 3136 + col];
    }
    __syncthreads();
    int wi = xsrow / 7, pi = xsrow - wi * 7;
    for (int j = threadIdx.x; j < 32 * 56; j += blockDim.x) {
        int cw = j & 31, pos = j >> 5;
        int wj = pos / 7, pj = pos - wj * 7;
        int col = pos + 3; if (col >= 56) col -= 56;
        int token = (b * 64 + wi * 8 + wj) * 49 + pi * 7 + pj;
        g_xw[(size_t)token * 256 + c0 + cw] = s[cw * 57 + col];
    }
}

// ---------------- kernel 2: mask ----------------
__global__ void mask_kernel(const float* __restrict__ pe) {
    int n = blockIdx.x;
    for (int e = threadIdx.x; e < 2401; e += blockDim.x) {
        int i = e / 49, j = e - i * 49;
        int i7 = i % 7, j7 = j % 7;
        int r0 = j / 7 - i / 7 + 6;
        int r1 = j7 - i7 + 6;
        float v = pe[r0 * 13 + r1];
        if (n >= 56 && ((i >= 28) != (j >= 28))) v = NEG_INF;
        if ((n == 55 || n == 63) && ((i7 >= 4) != (j7 >= 4))) v = NEG_INF;
        g_mask[n * 2401 + e] = v;
    }
}

// ---------------- kernel 3: QKV GEMM, block 128x128, warp 64x32, dbl-buffered ----------------
__global__ __launch_bounds__(256, 2) void gemm_qkv_tc(const float* __restrict__ wqkv) {
    __shared__ unsigned As[2][128 * 20];
    __shared__ unsigned Bs[2][128 * 20];
    int n0 = blockIdx.x * 128;
    int m0 = blockIdx.y * 128;
    int tid = threadIdx.x;
    int lane = tid & 31, wid = tid >> 5;
    int g = lane >> 2, t = lane & 3;
    int wm = (wid & 1) * 64, wn = (wid >> 1) * 32;

    int arow = tid >> 1, acol = (tid & 1) * 8;
    int bkk = tid & 15, bng = tid >> 4;

    float acc[4][4][4];
#pragma unroll
    for (int mf = 0; mf < 4; mf++)
#pragma unroll
        for (int nf = 0; nf < 4; nf++)
#pragma unroll
            for (int v = 0; v < 4; v++) acc[mf][nf][v] = 0.f;

    const float* Ab = g_xw + (size_t)(m0 + arow) * 256 + acol;
    const float* Bb = wqkv + (size_t)bkk * 768 + n0 + bng * 8;

#define STAGE_QKV(kc, buf) {                                                   \
    int k0 = (kc) * 16;                                                        \
    float4 a0 = *(const float4*)(Ab + k0);                                     \
    float4 a1 = *(const float4*)(Ab + k0 + 4);                                 \
    unsigned* ap = &As[buf][arow * 20 + acol];                                 \
    ap[0]=f2tf(a0.x); ap[1]=f2tf(a0.y); ap[2]=f2tf(a0.z); ap[3]=f2tf(a0.w);    \
    ap[4]=f2tf(a1.x); ap[5]=f2tf(a1.y); ap[6]=f2tf(a1.z); ap[7]=f2tf(a1.w);    \
    float4 b0 = *(const float4*)(Bb + (size_t)k0 * 768);                       \
    float4 b1 = *(const float4*)(Bb + (size_t)k0 * 768 + 4);                   \
    unsigned* bp = &Bs[buf][bng * 8 * 20 + bkk];                               \
    bp[0]=f2tf(b0.x); bp[20]=f2tf(b0.y); bp[40]=f2tf(b0.z); bp[60]=f2tf(b0.w); \
    bp[80]=f2tf(b1.x); bp[100]=f2tf(b1.y); bp[120]=f2tf(b1.z); bp[140]=f2tf(b1.w); }

    STAGE_QKV(0, 0);
    __syncthreads();
    for (int kc = 0; kc < 16; kc++) {
        int buf = kc & 1;
        if (kc < 15) STAGE_QKV(kc + 1, buf ^ 1);
#pragma unroll
        for (int kf = 0; kf < 2; kf++) {
            unsigned a[4][4], b[4][2];
#pragma unroll
            for (int mf = 0; mf < 4; mf++) {
                int base = (wm + mf * 16 + g) * 20 + kf * 8 + t;
                a[mf][0] = As[buf][base];
                a[mf][1] = As[buf][base + 160];
                a[mf][2] = As[buf][base + 4];
                a[mf][3] = As[buf][base + 164];
            }
#pragma unroll
            for (int nf = 0; nf < 4; nf++) {
                int bb = (wn + nf * 8 + g) * 20 + kf * 8 + t;
                b[nf][0] = Bs[buf][bb];
                b[nf][1] = Bs[buf][bb + 4];
            }
#pragma unroll
            for (int mf = 0; mf < 4; mf++)
#pragma unroll
                for (int nf = 0; nf < 4; nf++)
                    mma_tf32(acc[mf][nf], a[mf], b[nf]);
        }
        __syncthreads();
    }

    int mat = n0 >> 8;   // 128-tile never straddles q/k/v boundary
    float* dst = g_qkv + (size_t)mat * QS;
#pragma unroll
    for (int mf = 0; mf < 4; mf++) {
        int row0 = m0 + wm + mf * 16 + g;
        int bn0 = row0 / 49, tk0 = row0 - bn0 * 49;
        int row1 = row0 + 8;
        int bn1 = row1 / 49, tk1 = row1 - bn1 * 49;
#pragma unroll
        for (int nf = 0; nf < 4; nf++) {
            int ncol = (n0 + wn + nf * 8 + 2 * t) & 255;
            int head = ncol >> 5, dh = ncol & 31;
            *(float2*)&dst[(size_t)((bn0 * 8 + head) * 49 + tk0) * 32 + dh] =
                make_float2(acc[mf][nf][0], acc[mf][nf][1]);
            *(float2*)&dst[(size_t)((bn1 * 8 + head) * 49 + tk1) * 32 + dh] =
                make_float2(acc[mf][nf][2], acc[mf][nf][3]);
        }
    }
}

// ---------------- kernel 4: fused attention + output projection ----------------
// 512 threads = 4 quads x 4 warps. quad q handles heads q and q+4.
// Osm: 64x260 tf32; quad buffers: Qs(64x36)|Ks(56x36)|Vt(32x60); Ps aliases Qs.
#define OSM_U32   (64 * 260)
#define QBUF_U32  6240
#define SMEM_U32  (OSM_U32 + 4 * QBUF_U32)

__global__ __launch_bounds__(512, 1) void attn_proj(float* __restrict__ dout,
                                                    const float* __restrict__ wout,
                                                    const float* __restrict__ bout) {
    extern __shared__ unsigned sm[];
    unsigned* Osm = sm;
    unsigned* qbase = sm + OSM_U32;

    int bn = blockIdx.x, n = bn & 63;
    int tid = threadIdx.x, lane = tid & 31, wid = tid >> 5;
    int quad = wid >> 2, w4 = wid & 3;
    int qtid = tid & 127;
    int g = lane >> 2, t = lane & 3;

    unsigned* Qs = qbase + quad * QBUF_U32;
    unsigned* Ks = Qs + 64 * 36;
    unsigned* Vt = Qs + 4320;
    unsigned* Ps = Qs;

    // zero pads once: Qs rows 49..63 (540), Ks rows 49..55 (252), Vt all (1920)
    for (int i = qtid; i < 2712; i += 128) {
        if (i < 540) Qs[49 * 36 + i] = 0;
        else if (i < 792) Ks[49 * 36 + (i - 540)] = 0;
        else Vt[i - 792] = 0;
    }
    barq(quad + 1);

    const float scale = 0.17677669529663687f;
    const float* mk = g_mask + n * 2401;
    int row0 = w4 * 16 + g, row1 = row0 + 8;

    for (int hi = 0; hi < 2; hi++) {
        int h = hi * 4 + quad;
        const float* qg = g_qkv + (size_t)((bn * 8 + h) * 49) * 32;
        const float* kg = qg + (size_t)QS;
        const float* vg = qg + (size_t)2 * QS;
        for (int i4 = qtid; i4 < 392; i4 += 128) {
            int tk = i4 >> 3, d4 = (i4 & 7) * 4;
            float4 q = *(const float4*)(qg + tk * 32 + d4);
            float4 k = *(const float4*)(kg + tk * 32 + d4);
            float4 v = *(const float4*)(vg + tk * 32 + d4);
            unsigned* qp = &Qs[tk * 36 + d4];
            qp[0] = f2tf(q.x); qp[1] = f2tf(q.y); qp[2] = f2tf(q.z); qp[3] = f2tf(q.w);
            unsigned* kp = &Ks[tk * 36 + d4];
            kp[0] = f2tf(k.x); kp[1] = f2tf(k.y); kp[2] = f2tf(k.z); kp[3] = f2tf(k.w);
            Vt[(d4 + 0) * 60 + tk] = f2tf(v.x);
            Vt[(d4 + 1) * 60 + tk] = f2tf(v.y);
            Vt[(d4 + 2) * 60 + tk] = f2tf(v.z);
            Vt[(d4 + 3) * 60 + tk] = f2tf(v.w);
        }
        barq(quad + 1);

        // S = Q @ K^T
        float s[7][4];
#pragma unroll
        for (int nf = 0; nf < 7; nf++)
#pragma unroll
            for (int v = 0; v < 4; v++) s[nf][v] = 0.f;
#pragma unroll
        for (int kf = 0; kf < 4; kf++) {
            unsigned a[4];
            int base = (w4 * 16 + g) * 36 + kf * 8 + t;
            a[0] = Qs[base]; a[1] = Qs[base + 8 * 36];
            a[2] = Qs[base + 4]; a[3] = Qs[base + 8 * 36 + 4];
#pragma unroll
            for (int nf = 0; nf < 7; nf++) {
                unsigned b[2];
                int bb = (nf * 8 + g) * 36 + kf * 8 + t;
                b[0] = Ks[bb]; b[1] = Ks[bb + 4];
                mma_tf32(s[nf], a, b);
            }
        }

        // scale + mask
#pragma unroll
        for (int nf = 0; nf < 7; nf++) {
            int c0 = nf * 8 + 2 * t, c1 = c0 + 1;
            float m00 = (c0 < 49) ? ((row0 < 49) ? __ldg(mk + row0 * 49 + c0) : 0.f) : NEG_INF;
            float m01 = (c1 < 49) ? ((row0 < 49) ? __ldg(mk + row0 * 49 + c1) : 0.f) : NEG_INF;
            float m10 = (c0 < 49) ? ((row1 < 49) ? __ldg(mk + row1 * 49 + c0) : 0.f) : NEG_INF;
            float m11 = (c1 < 49) ? ((row1 < 49) ? __ldg(mk + row1 * 49 + c1) : 0.f) : NEG_INF;
            s[nf][0] = s[nf][0] * scale + m00;
            s[nf][1] = s[nf][1] * scale + m01;
            s[nf][2] = s[nf][2] * scale + m10;
            s[nf][3] = s[nf][3] * scale + m11;
        }

        // softmax (rows split across 4 lanes of a group)
        float mx0 = NEG_INF, mx1 = NEG_INF;
#pragma unroll
        for (int nf = 0; nf < 7; nf++) {
            mx0 = fmaxf(mx0, fmaxf(s[nf][0], s[nf][1]));
            mx1 = fmaxf(mx1, fmaxf(s[nf][2], s[nf][3]));
        }
        mx0 = fmaxf(mx0, __shfl_xor_sync(0xffffffffu, mx0, 1));
        mx0 = fmaxf(mx0, __shfl_xor_sync(0xffffffffu, mx0, 2));
        mx1 = fmaxf(mx1, __shfl_xor_sync(0xffffffffu, mx1, 1));
        mx1 = fmaxf(mx1, __shfl_xor_sync(0xffffffffu, mx1, 2));
        float sm0 = 0.f, sm1 = 0.f;
#pragma unroll
        for (int nf = 0; nf < 7; nf++) {
            s[nf][0] = __expf(s[nf][0] - mx0);
            s[nf][1] = __expf(s[nf][1] - mx0);
            s[nf][2] = __expf(s[nf][2] - mx1);
            s[nf][3] = __expf(s[nf][3] - mx1);
            sm0 += s[nf][0] + s[nf][1];
            sm1 += s[nf][2] + s[nf][3];
        }
        sm0 += __shfl_xor_sync(0xffffffffu, sm0, 1);
        sm0 += __shfl_xor_sync(0xffffffffu, sm0, 2);
        sm1 += __shfl_xor_sync(0xffffffffu, sm1, 1);
        sm1 += __shfl_xor_sync(0xffffffffu, sm1, 2);
        float inv0 = 1.f / sm0, inv1 = 1.f / sm1;
#pragma unroll
        for (int nf = 0; nf < 7; nf++) {
            s[nf][0] *= inv0; s[nf][1] *= inv0;
            s[nf][2] *= inv1; s[nf][3] *= inv1;
        }
        barq(quad + 1);   // all quad warps done reading Qs/Ks before Ps overwrite

        // write attn output + Ps
        float* ao = dout + (size_t)OUT_ELEMS + (size_t)((bn * 8 + h) * 49) * 49;
#pragma unroll
        for (int nf = 0; nf < 7; nf++) {
            int c0 = nf * 8 + 2 * t;
            if (row0 < 49) {
                if (c0 < 49) ao[row0 * 49 + c0] = s[nf][0];
                if (c0 + 1 < 49) ao[row0 * 49 + c0 + 1] = s[nf][1];
            }
            if (row1 < 49) {
                if (c0 < 49) ao[row1 * 49 + c0] = s[nf][2];
                if (c0 + 1 < 49) ao[row1 * 49 + c0 + 1] = s[nf][3];
            }
            *(uint2*)&Ps[row0 * 60 + c0] = make_uint2(f2tf(s[nf][0]), f2tf(s[nf][1]));
            *(uint2*)&Ps[row1 * 60 + c0] = make_uint2(f2tf(s[nf][2]), f2tf(s[nf][3]));
        }
        barq(quad + 1);

        // O = P @ V  -> Osm columns h*32..h*32+31 (tf32)
        float o[4][4];
#pragma unroll
        for (int nf = 0; nf < 4; nf++)
#pragma unroll
            for (int v = 0; v < 4; v++) o[nf][v] = 0.f;
#pragma unroll
        for (int kf = 0; kf < 7; kf++) {
            unsigned a[4];
            int base = (w4 * 16 + g) * 60 + kf * 8 + t;
            a[0] = Ps[base]; a[1] = Ps[base + 8 * 60];
            a[2] = Ps[base + 4]; a[3] = Ps[base + 8 * 60 + 4];
#pragma unroll
            for (int nf = 0; nf < 4; nf++) {
                unsigned b[2];
                int bb = (nf * 8 + g) * 60 + kf * 8 + t;
                b[0] = Vt[bb]; b[1] = Vt[bb + 4];
                mma_tf32(o[nf], a, b);
            }
        }
#pragma unroll
        for (int nf = 0; nf < 4; nf++) {
            int col = h * 32 + nf * 8 + 2 * t;
            if (row0 < 49)
                *(uint2*)&Osm[row0 * 260 + col] = make_uint2(f2tf(o[nf][0]), f2tf(o[nf][1]));
            if (row1 < 49)
                *(uint2*)&Osm[row1 * 260 + col] = make_uint2(f2tf(o[nf][2]), f2tf(o[nf][3]));
        }
        barq(quad + 1);   // done reading Ps/Vt before next head's loads
    }

    // zero pad rows of Osm (rows 49..63) so proj A-frags are clean
    for (int i = tid; i < 15 * 260; i += 512) Osm[49 * 260 + i] = 0;
    __syncthreads();

    // ---- projection: C[64,256] = Osm @ wout + bias -> g_otok ----
    unsigned* BsP = qbase;   // double buffer 2 x 256*20, aliases quad buffers
    int wm2 = (wid & 1) * 32, wn = (wid >> 1) * 32;
    int bkk = tid & 15, bng = tid >> 4;   // bng 0..31, cols bng*8..+7

    float acc[2][4][4];
#pragma unroll
    for (int mf = 0; mf < 2; mf++)
#pragma unroll
        for (int nf = 0; nf < 4; nf++)
#pragma unroll
            for (int v = 0; v < 4; v++) acc[mf][nf][v] = 0.f;

#define STAGE_W(kc, buf) {                                                      \
    const float* Bb = wout + (size_t)((kc) * 16 + bkk) * 256 + bng * 8;         \
    float4 b0 = *(const float4*)Bb;                                             \
    float4 b1 = *(const float4*)(Bb + 4);                                       \
    unsigned* bp = &BsP[(buf) * 5120 + bng * 8 * 20 + bkk];                     \
    bp[0]=f2tf(b0.x); bp[20]=f2tf(b0.y); bp[40]=f2tf(b0.z); bp[60]=f2tf(b0.w);  \
    bp[80]=f2tf(b1.x); bp[100]=f2tf(b1.y); bp[120]=f2tf(b1.z); bp[140]=f2tf(b1.w); }

    STAGE_W(0, 0);
    __syncthreads();
    for (int kc = 0; kc < 16; kc++) {
        int buf = kc & 1;
        if (kc < 15) STAGE_W(kc + 1, buf ^ 1);
#pragma unroll
        for (int kf = 0; kf < 2; kf++) {
            unsigned a[2][4], b[4][2];
#pragma unroll
            for (int mf = 0; mf < 2; mf++) {
                int base = (wm2 + mf * 16 + g) * 260 + kc * 16 + kf * 8 + t;
                a[mf][0] = Osm[base];
                a[mf][1] = Osm[base + 8 * 260];
                a[mf][2] = Osm[base + 4];
                a[mf][3] = Osm[base + 8 * 260 + 4];
            }
#pragma unroll
            for (int nf = 0; nf < 4; nf++) {
                int bb = buf * 5120 + (wn + nf * 8 + g) * 20 + kf * 8 + t;
                b[nf][0] = BsP[bb];
                b[nf][1] = BsP[bb + 4];
            }
#pragma unroll
            for (int mf = 0; mf < 2; mf++)
#pragma unroll
                for (int nf = 0; nf < 4; nf++)
                    mma_tf32(acc[mf][nf], a[mf], b[nf]);
        }
        __syncthreads();
    }

#pragma unroll
    for (int mf = 0; mf < 2; mf++) {
        int r0 = wm2 + mf * 16 + g, r1 = r0 + 8;
#pragma unroll
        for (int nf = 0; nf < 4; nf++) {
            int ncol = wn + nf * 8 + 2 * t;
            float2 bv = *(const float2*)&bout[ncol];
            if (r0 < 49)
                *(float2*)&g_otok[(size_t)(bn * 49 + r0) * 256 + ncol] =
                    make_float2(acc[mf][nf][0] + bv.x, acc[mf][nf][1] + bv.y);
            if (r1 < 49)
                *(float2*)&g_otok[(size_t)(bn * 49 + r1) * 256 + ncol] =
                    make_float2(acc[mf][nf][2] + bv.x, acc[mf][nf][3] + bv.y);
        }
    }
}

// ---------------- kernel 5: scatter ----------------
__global__ void scatter_kernel(float* __restrict__ out) {
    __shared__ float s[32 * 57];
    int xsrow = blockIdx.x;
    int c0 = blockIdx.y * 32;
    int b = blockIdx.z;
    int wi = xsrow / 7, pi = xsrow - wi * 7;
    for (int j = threadIdx.x; j < 32 * 56; j += blockDim.x) {
        int cw = j & 31, pos = j >> 5;
        int wj = pos / 7, pj = pos - wj * 7;
        int col = pos + 3; if (col >= 56) col -= 56;
        int token = (b * 64 + wi * 8 + wj) * 49 + pi * 7 + pj;
        s[cw * 57 + col] = g_otok[(size_t)token * 256 + c0 + cw];
    }
    __syncthreads();
    int r = xsrow + 3; if (r >= 56) r -= 56;
    float* ob = out + ((size_t)(b * 256 + c0) * 3136) + r * 56;
    for (int i = threadIdx.x; i < 32 * 56; i += blockDim.x) {
        int c = i / 56, col = i - c * 56;
        ob[(size_t)c * 3136 + col] = s[c * 57 + col];
    }
}

// ---------------- launch ----------------
extern "C" void kernel_launch(void* const* d_in, const int* in_sizes, int n_in,
                              void* d_out, int out_size) {
    const float* x    = (const float*)d_in[0];
    const float* pe   = (const float*)d_in[1];
    const float* wqkv = (const float*)d_in[2];
    const float* wout = (const float*)d_in[3];
    const float* bout = (const float*)d_in[4];
    float* out = (float*)d_out;

    cudaFuncSetAttribute(attn_proj, cudaFuncAttributeMaxDynamicSharedMemorySize,
                         SMEM_U32 * 4);

    gather_kernel<<<dim3(56, 8, 32), 256>>>(x);
    mask_kernel<<<64, 256>>>(pe);
    gemm_qkv_tc<<<dim3(6, 784), 256>>>(wqkv);
    attn_proj<<<BNW, 512, SMEM_U32 * 4>>>(out, wout, bout);
    scatter_kernel<<<dim3(56, 8, 32), 256>>>(out);
}

// round 8
// speedup vs baseline: 1.0658x; 1.0658x over previous
#include <cuda_runtime.h>
#include <cstdint>

// ---------------- problem constants ----------------
#define B_      32
#define PP      49
#define NW      64
#define BNW     2048
#define MTOK    100352                 // BNW*49
#define QS      25690112               // BNW*8*49*32
#define OUT_ELEMS 25690112

#define NEG_INF __int_as_float(0xff800000)

// ---------------- scratch ----------------
__device__ float g_xw[(size_t)MTOK * 256];
__device__ float g_qkv[(size_t)3 * QS];
__device__ float g_oattn[(size_t)MTOK * 256];
__device__ float g_otok[(size_t)MTOK * 256];
__device__ float g_mask[NW * PP * PP];

// ---------------- tf32 helpers ----------------
__device__ __forceinline__ unsigned f2tf(float f) {
    unsigned u; asm("cvt.rna.tf32.f32 %0, %1;" : "=r"(u) : "f"(f)); return u;
}
// D += A(16x8)*B(8x8) tf32, f32 accum. g=lane>>2, t=lane&3.
__device__ __forceinline__ void mma_tf32(float* c, const unsigned* a, const unsigned* b) {
    asm volatile("mma.sync.aligned.m16n8k8.row.col.f32.tf32.tf32.f32 "
        "{%0,%1,%2,%3}, {%4,%5,%6,%7}, {%8,%9}, {%0,%1,%2,%3};"
        : "+f"(c[0]), "+f"(c[1]), "+f"(c[2]), "+f"(c[3])
        : "r"(a[0]), "r"(a[1]), "r"(a[2]), "r"(a[3]), "r"(b[0]), "r"(b[1]));
}

// ---------------- kernel 1: gather + roll(-3) + window permute ----------------
__global__ void gather_kernel(const float* __restrict__ x) {
    __shared__ float s[32 * 57];
    int xsrow = blockIdx.x;
    int c0 = blockIdx.y * 32;
    int b = blockIdx.z;
    int r = xsrow + 3; if (r >= 56) r -= 56;
    const float* xb = x + ((size_t)(b * 256 + c0) * 3136) + r * 56;
    for (int i = threadIdx.x; i < 32 * 56; i += blockDim.x) {
        int c = i / 56, col = i - c * 56;
        s[c * 57 + col] = xb[(size_t)c * 3136 + col];
    }
    __syncthreads();
    int wi = xsrow / 7, pi = xsrow - wi * 7;
    for (int j = threadIdx.x; j < 32 * 56; j += blockDim.x) {
        int cw = j & 31, pos = j >> 5;
        int wj = pos / 7, pj = pos - wj * 7;
        int col = pos + 3; if (col >= 56) col -= 56;
        int token = (b * 64 + wi * 8 + wj) * 49 + pi * 7 + pj;
        g_xw[(size_t)token * 256 + c0 + cw] = s[cw * 57 + col];
    }
}

// ---------------- kernel 2: mask ----------------
__global__ void mask_kernel(const float* __restrict__ pe) {
    int n = blockIdx.x;
    for (int e = threadIdx.x; e < 2401; e += blockDim.x) {
        int i = e / 49, j = e - i * 49;
        int i7 = i % 7, j7 = j % 7;
        int r0 = j / 7 - i / 7 + 6;
        int r1 = j7 - i7 + 6;
        float v = pe[r0 * 13 + r1];
        if (n >= 56 && ((i >= 28) != (j >= 28))) v = NEG_INF;
        if ((n == 55 || n == 63) && ((i7 >= 4) != (j7 >= 4))) v = NEG_INF;
        g_mask[n * 2401 + e] = v;
    }
}

// ================= swizzled-smem tf32 GEMM (128x128 block, 64x32 warp) =================
// smem chunk layout: per row, 16 k-words; word q = 4*((k&3)^(row&3)) + (k>>2).
// One LDS.128 at word (row*16 + 4*(t^(row&3))) returns k = {t, t+4, t+8, t+12}.

// ---------------- kernel 3: QKV GEMM ----------------
__global__ __launch_bounds__(256, 2) void gemm_qkv_tc(const float* __restrict__ wqkv) {
    __shared__ __align__(16) unsigned As[2][2048];
    __shared__ __align__(16) unsigned Bs[2][2048];
    int n0 = blockIdx.x * 128;
    int m0 = blockIdx.y * 128;
    int tid = threadIdx.x;
    int lane = tid & 31, wid = tid >> 5;
    int g = lane >> 2, t = lane & 3;
    int wm = (wid & 1) * 64, wn = (wid >> 1) * 32;

    int arow = tid >> 1, acol = (tid & 1) * 8;
    int bkk = tid & 15, bng = tid >> 4;

    float acc[4][4][4];
#pragma unroll
    for (int mf = 0; mf < 4; mf++)
#pragma unroll
        for (int nf = 0; nf < 4; nf++)
#pragma unroll
            for (int v = 0; v < 4; v++) acc[mf][nf][v] = 0.f;

    const float* Ab = g_xw + (size_t)(m0 + arow) * 256;
    const float* Bb = wqkv + n0 + bng * 8;

    auto stage = [&](int kc, int buf) {
        float4 a0 = *(const float4*)(Ab + kc * 16 + acol);
        float4 a1 = *(const float4*)(Ab + kc * 16 + acol + 4);
        float av[8] = {a0.x, a0.y, a0.z, a0.w, a1.x, a1.y, a1.z, a1.w};
#pragma unroll
        for (int i = 0; i < 8; i++) {
            int k = acol + i;
            int q = 4 * ((k & 3) ^ (arow & 3)) + (k >> 2);
            As[buf][arow * 16 + q] = f2tf(av[i]);
        }
        float4 b0 = *(const float4*)(Bb + (size_t)(kc * 16 + bkk) * 768);
        float4 b1 = *(const float4*)(Bb + (size_t)(kc * 16 + bkk) * 768 + 4);
        float bv[8] = {b0.x, b0.y, b0.z, b0.w, b1.x, b1.y, b1.z, b1.w};
#pragma unroll
        for (int c = 0; c < 8; c++) {
            int col = bng * 8 + c;
            int q = 4 * ((bkk & 3) ^ (col & 3)) + (bkk >> 2);
            Bs[buf][col * 16 + q] = f2tf(bv[c]);
        }
    };

    stage(0, 0);
    __syncthreads();
    for (int kc = 0; kc < 16; kc++) {
        int buf = kc & 1;
        if (kc < 15) stage(kc + 1, buf ^ 1);
        uint4 Af[4][2], Bf[4];
        const uint4* Ap = (const uint4*)As[buf];
        const uint4* Bp = (const uint4*)Bs[buf];
        int sw = t ^ (g & 3);
#pragma unroll
        for (int mf = 0; mf < 4; mf++) {
            int r = wm + mf * 16 + g;
            Af[mf][0] = Ap[r * 4 + sw];
            Af[mf][1] = Ap[(r + 8) * 4 + sw];
        }
#pragma unroll
        for (int nf = 0; nf < 4; nf++) {
            int cn = wn + nf * 8 + g;
            Bf[nf] = Bp[cn * 4 + sw];
        }
#pragma unroll
        for (int kf = 0; kf < 2; kf++) {
#pragma unroll
            for (int mf = 0; mf < 4; mf++) {
                unsigned a[4];
                if (kf == 0) { a[0]=Af[mf][0].x; a[1]=Af[mf][1].x; a[2]=Af[mf][0].y; a[3]=Af[mf][1].y; }
                else         { a[0]=Af[mf][0].z; a[1]=Af[mf][1].z; a[2]=Af[mf][0].w; a[3]=Af[mf][1].w; }
#pragma unroll
                for (int nf = 0; nf < 4; nf++) {
                    unsigned b[2];
                    if (kf == 0) { b[0]=Bf[nf].x; b[1]=Bf[nf].y; }
                    else         { b[0]=Bf[nf].z; b[1]=Bf[nf].w; }
                    mma_tf32(acc[mf][nf], a, b);
                }
            }
        }
        __syncthreads();
    }

    int mat = n0 >> 8;   // 128-wide tile never straddles the q/k/v boundary
    float* dst = g_qkv + (size_t)mat * QS;
#pragma unroll
    for (int mf = 0; mf < 4; mf++) {
        int row0 = m0 + wm + mf * 16 + g;
        int bn0 = row0 / 49, tk0 = row0 - bn0 * 49;
        int row1 = row0 + 8;
        int bn1 = row1 / 49, tk1 = row1 - bn1 * 49;
#pragma unroll
        for (int nf = 0; nf < 4; nf++) {
            int ncol = (n0 + wn + nf * 8 + 2 * t) & 255;
            int head = ncol >> 5, dh = ncol & 31;
            *(float2*)&dst[(size_t)((bn0 * 8 + head) * 49 + tk0) * 32 + dh] =
                make_float2(acc[mf][nf][0], acc[mf][nf][1]);
            *(float2*)&dst[(size_t)((bn1 * 8 + head) * 49 + tk1) * 32 + dh] =
                make_float2(acc[mf][nf][2], acc[mf][nf][3]);
        }
    }
}

// ---------------- kernel 4: attention (tf32 MMA) — R3 version ----------------
__global__ __launch_bounds__(128) void attn_tc(float* __restrict__ dout) {
    __shared__ unsigned SBuf[4320];        // Qs[64*36] | Ks[56*36]; Ps[64*60] aliases
    __shared__ unsigned Vt[32 * 60];
    unsigned* Qs = SBuf;
    unsigned* Ks = SBuf + 64 * 36;
    unsigned* Ps = SBuf;

    int bn = blockIdx.x >> 3, h = blockIdx.x & 7, n = bn & 63;
    int tid = threadIdx.x, lane = tid & 31, w = tid >> 5;
    int g = lane >> 2, t = lane & 3;

    const float* qg = g_qkv + (size_t)((bn * 8 + h) * 49) * 32;
    const float* kg = qg + (size_t)QS;
    const float* vg = qg + (size_t)2 * QS;

    for (int i = tid; i < 2712; i += 128) {
        if (i < 540) Qs[49 * 36 + i] = 0;
        else if (i < 792) Ks[49 * 36 + (i - 540)] = 0;
        else Vt[i - 792] = 0;
    }
    __syncthreads();
    for (int i4 = tid; i4 < 392; i4 += 128) {
        int tk = i4 >> 3, d4 = (i4 & 7) * 4;
        float4 q = *(const float4*)(qg + tk * 32 + d4);
        float4 k = *(const float4*)(kg + tk * 32 + d4);
        float4 v = *(const float4*)(vg + tk * 32 + d4);
        unsigned* qp = &Qs[tk * 36 + d4];
        qp[0] = f2tf(q.x); qp[1] = f2tf(q.y); qp[2] = f2tf(q.z); qp[3] = f2tf(q.w);
        unsigned* kp = &Ks[tk * 36 + d4];
        kp[0] = f2tf(k.x); kp[1] = f2tf(k.y); kp[2] = f2tf(k.z); kp[3] = f2tf(k.w);
        Vt[(d4 + 0) * 60 + tk] = f2tf(v.x);
        Vt[(d4 + 1) * 60 + tk] = f2tf(v.y);
        Vt[(d4 + 2) * 60 + tk] = f2tf(v.z);
        Vt[(d4 + 3) * 60 + tk] = f2tf(v.w);
    }
    __syncthreads();

    float s[7][4];
#pragma unroll
    for (int nf = 0; nf < 7; nf++)
#pragma unroll
        for (int v = 0; v < 4; v++) s[nf][v] = 0.f;
#pragma unroll
    for (int kf = 0; kf < 4; kf++) {
        unsigned a[4];
        int base = (w * 16 + g) * 36 + kf * 8 + t;
        a[0] = Qs[base]; a[1] = Qs[base + 8 * 36];
        a[2] = Qs[base + 4]; a[3] = Qs[base + 8 * 36 + 4];
#pragma unroll
        for (int nf = 0; nf < 7; nf++) {
            unsigned b[2];
            int bb = (nf * 8 + g) * 36 + kf * 8 + t;
            b[0] = Ks[bb]; b[1] = Ks[bb + 4];
            mma_tf32(s[nf], a, b);
        }
    }

    const float scale = 0.17677669529663687f;
    const float* mk = g_mask + n * 2401;
    int row0 = w * 16 + g, row1 = row0 + 8;
#pragma unroll
    for (int nf = 0; nf < 7; nf++) {
        int c0 = nf * 8 + 2 * t, c1 = c0 + 1;
        float m00 = (c0 < 49) ? ((row0 < 49) ? __ldg(mk + row0 * 49 + c0) : 0.f) : NEG_INF;
        float m01 = (c1 < 49) ? ((row0 < 49) ? __ldg(mk + row0 * 49 + c1) : 0.f) : NEG_INF;
        float m10 = (c0 < 49) ? ((row1 < 49) ? __ldg(mk + row1 * 49 + c0) : 0.f) : NEG_INF;
        float m11 = (c1 < 49) ? ((row1 < 49) ? __ldg(mk + row1 * 49 + c1) : 0.f) : NEG_INF;
        s[nf][0] = s[nf][0] * scale + m00;
        s[nf][1] = s[nf][1] * scale + m01;
        s[nf][2] = s[nf][2] * scale + m10;
        s[nf][3] = s[nf][3] * scale + m11;
    }

    float mx0 = NEG_INF, mx1 = NEG_INF;
#pragma unroll
    for (int nf = 0; nf < 7; nf++) {
        mx0 = fmaxf(mx0, fmaxf(s[nf][0], s[nf][1]));
        mx1 = fmaxf(mx1, fmaxf(s[nf][2], s[nf][3]));
    }
    mx0 = fmaxf(mx0, __shfl_xor_sync(0xffffffffu, mx0, 1));
    mx0 = fmaxf(mx0, __shfl_xor_sync(0xffffffffu, mx0, 2));
    mx1 = fmaxf(mx1, __shfl_xor_sync(0xffffffffu, mx1, 1));
    mx1 = fmaxf(mx1, __shfl_xor_sync(0xffffffffu, mx1, 2));
    float sm0 = 0.f, sm1 = 0.f;
#pragma unroll
    for (int nf = 0; nf < 7; nf++) {
        s[nf][0] = __expf(s[nf][0] - mx0);
        s[nf][1] = __expf(s[nf][1] - mx0);
        s[nf][2] = __expf(s[nf][2] - mx1);
        s[nf][3] = __expf(s[nf][3] - mx1);
        sm0 += s[nf][0] + s[nf][1];
        sm1 += s[nf][2] + s[nf][3];
    }
    sm0 += __shfl_xor_sync(0xffffffffu, sm0, 1);
    sm0 += __shfl_xor_sync(0xffffffffu, sm0, 2);
    sm1 += __shfl_xor_sync(0xffffffffu, sm1, 1);
    sm1 += __shfl_xor_sync(0xffffffffu, sm1, 2);
    float inv0 = 1.f / sm0, inv1 = 1.f / sm1;
#pragma unroll
    for (int nf = 0; nf < 7; nf++) {
        s[nf][0] *= inv0; s[nf][1] *= inv0;
        s[nf][2] *= inv1; s[nf][3] *= inv1;
    }

    __syncthreads();

    float* ao = dout + (size_t)OUT_ELEMS + (size_t)((bn * 8 + h) * 49) * 49;
#pragma unroll
    for (int nf = 0; nf < 7; nf++) {
        int c0 = nf * 8 + 2 * t;
        if (row0 < 49) {
            if (c0 < 49) ao[row0 * 49 + c0] = s[nf][0];
            if (c0 + 1 < 49) ao[row0 * 49 + c0 + 1] = s[nf][1];
        }
        if (row1 < 49) {
            if (c0 < 49) ao[row1 * 49 + c0] = s[nf][2];
            if (c0 + 1 < 49) ao[row1 * 49 + c0 + 1] = s[nf][3];
        }
        *(uint2*)&Ps[row0 * 60 + c0] = make_uint2(f2tf(s[nf][0]), f2tf(s[nf][1]));
        *(uint2*)&Ps[row1 * 60 + c0] = make_uint2(f2tf(s[nf][2]), f2tf(s[nf][3]));
    }
    __syncthreads();

    float o[4][4];
#pragma unroll
    for (int nf = 0; nf < 4; nf++)
#pragma unroll
        for (int v = 0; v < 4; v++) o[nf][v] = 0.f;
#pragma unroll
    for (int kf = 0; kf < 7; kf++) {
        unsigned a[4];
        int base = (w * 16 + g) * 60 + kf * 8 + t;
        a[0] = Ps[base]; a[1] = Ps[base + 8 * 60];
        a[2] = Ps[base + 4]; a[3] = Ps[base + 8 * 60 + 4];
#pragma unroll
        for (int nf = 0; nf < 4; nf++) {
            unsigned b[2];
            int bb = (nf * 8 + g) * 60 + kf * 8 + t;
            b[0] = Vt[bb]; b[1] = Vt[bb + 4];
            mma_tf32(o[nf], a, b);
        }
    }
#pragma unroll
    for (int nf = 0; nf < 4; nf++) {
        int col = nf * 8 + 2 * t;
        if (row0 < 49)
            *(float2*)&g_oattn[((size_t)(bn * 49) + row0) * 256 + h * 32 + col] =
                make_float2(o[nf][0], o[nf][1]);
        if (row1 < 49)
            *(float2*)&g_oattn[((size_t)(bn * 49) + row1) * 256 + h * 32 + col] =
                make_float2(o[nf][2], o[nf][3]);
    }
}

// ---------------- kernel 5: output GEMM + bias (swizzled LDS.128) ----------------
__global__ __launch_bounds__(256, 2) void gemm_out_tc(const float* __restrict__ wout,
                                                      const float* __restrict__ bout) {
    __shared__ __align__(16) unsigned As[2][2048];
    __shared__ __align__(16) unsigned Bs[2][2048];
    int n0 = blockIdx.x * 128;
    int m0 = blockIdx.y * 128;
    int tid = threadIdx.x;
    int lane = tid & 31, wid = tid >> 5;
    int g = lane >> 2, t = lane & 3;
    int wm = (wid & 1) * 64, wn = (wid >> 1) * 32;

    int arow = tid >> 1, acol = (tid & 1) * 8;
    int bkk = tid & 15, bng = tid >> 4;

    float acc[4][4][4];
#pragma unroll
    for (int mf = 0; mf < 4; mf++)
#pragma unroll
        for (int nf = 0; nf < 4; nf++)
#pragma unroll
            for (int v = 0; v < 4; v++) acc[mf][nf][v] = 0.f;

    const float* Ab = g_oattn + (size_t)(m0 + arow) * 256;
    const float* Bb = wout + n0 + bng * 8;

    auto stage = [&](int kc, int buf) {
        float4 a0 = *(const float4*)(Ab + kc * 16 + acol);
        float4 a1 = *(const float4*)(Ab + kc * 16 + acol + 4);
        float av[8] = {a0.x, a0.y, a0.z, a0.w, a1.x, a1.y, a1.z, a1.w};
#pragma unroll
        for (int i = 0; i < 8; i++) {
            int k = acol + i;
            int q = 4 * ((k & 3) ^ (arow & 3)) + (k >> 2);
            As[buf][arow * 16 + q] = f2tf(av[i]);
        }
        float4 b0 = *(const float4*)(Bb + (size_t)(kc * 16 + bkk) * 256);
        float4 b1 = *(const float4*)(Bb + (size_t)(kc * 16 + bkk) * 256 + 4);
        float bv[8] = {b0.x, b0.y, b0.z, b0.w, b1.x, b1.y, b1.z, b1.w};
#pragma unroll
        for (int c = 0; c < 8; c++) {
            int col = bng * 8 + c;
            int q = 4 * ((bkk & 3) ^ (col & 3)) + (bkk >> 2);
            Bs[buf][col * 16 + q] = f2tf(bv[c]);
        }
    };

    stage(0, 0);
    __syncthreads();
    for (int kc = 0; kc < 16; kc++) {
        int buf = kc & 1;
        if (kc < 15) stage(kc + 1, buf ^ 1);
        uint4 Af[4][2], Bf[4];
        const uint4* Ap = (const uint4*)As[buf];
        const uint4* Bp = (const uint4*)Bs[buf];
        int sw = t ^ (g & 3);
#pragma unroll
        for (int mf = 0; mf < 4; mf++) {
            int r = wm + mf * 16 + g;
            Af[mf][0] = Ap[r * 4 + sw];
            Af[mf][1] = Ap[(r + 8) * 4 + sw];
        }
#pragma unroll
        for (int nf = 0; nf < 4; nf++) {
            int cn = wn + nf * 8 + g;
            Bf[nf] = Bp[cn * 4 + sw];
        }
#pragma unroll
        for (int kf = 0; kf < 2; kf++) {
#pragma unroll
            for (int mf = 0; mf < 4; mf++) {
                unsigned a[4];
                if (kf == 0) { a[0]=Af[mf][0].x; a[1]=Af[mf][1].x; a[2]=Af[mf][0].y; a[3]=Af[mf][1].y; }
                else         { a[0]=Af[mf][0].z; a[1]=Af[mf][1].z; a[2]=Af[mf][0].w; a[3]=Af[mf][1].w; }
#pragma unroll
                for (int nf = 0; nf < 4; nf++) {
                    unsigned b[2];
                    if (kf == 0) { b[0]=Bf[nf].x; b[1]=Bf[nf].y; }
                    else         { b[0]=Bf[nf].z; b[1]=Bf[nf].w; }
                    mma_tf32(acc[mf][nf], a, b);
                }
            }
        }
        __syncthreads();
    }

#pragma unroll
    for (int mf = 0; mf < 4; mf++) {
        int row0 = m0 + wm + mf * 16 + g;
#pragma unroll
        for (int nf = 0; nf < 4; nf++) {
            int ncol = n0 + wn + nf * 8 + 2 * t;
            float2 bv = *(const float2*)&bout[ncol];
            *(float2*)&g_otok[(size_t)row0 * 256 + ncol] =
                make_float2(acc[mf][nf][0] + bv.x, acc[mf][nf][1] + bv.y);
            *(float2*)&g_otok[(size_t)(row0 + 8) * 256 + ncol] =
                make_float2(acc[mf][nf][2] + bv.x, acc[mf][nf][3] + bv.y);
        }
    }
}

// ---------------- kernel 6: scatter ----------------
__global__ void scatter_kernel(float* __restrict__ out) {
    __shared__ float s[32 * 57];
    int xsrow = blockIdx.x;
    int c0 = blockIdx.y * 32;
    int b = blockIdx.z;
    int wi = xsrow / 7, pi = xsrow - wi * 7;
    for (int j = threadIdx.x; j < 32 * 56; j += blockDim.x) {
        int cw = j & 31, pos = j >> 5;
        int wj = pos / 7, pj = pos - wj * 7;
        int col = pos + 3; if (col >= 56) col -= 56;
        int token = (b * 64 + wi * 8 + wj) * 49 + pi * 7 + pj;
        s[cw * 57 + col] = g_otok[(size_t)token * 256 + c0 + cw];
    }
    __syncthreads();
    int r = xsrow + 3; if (r >= 56) r -= 56;
    float* ob = out + ((size_t)(b * 256 + c0) * 3136) + r * 56;
    for (int i = threadIdx.x; i < 32 * 56; i += blockDim.x) {
        int c = i / 56, col = i - c * 56;
        ob[(size_t)c * 3136 + col] = s[c * 57 + col];
    }
}

// ---------------- launch ----------------
extern "C" void kernel_launch(void* const* d_in, const int* in_sizes, int n_in,
                              void* d_out, int out_size) {
    const float* x    = (const float*)d_in[0];
    const float* pe   = (const float*)d_in[1];
    const float* wqkv = (const float*)d_in[2];
    const float* wout = (const float*)d_in[3];
    const float* bout = (const float*)d_in[4];
    float* out = (float*)d_out;

    gather_kernel<<<dim3(56, 8, 32), 256>>>(x);
    mask_kernel<<<64, 256>>>(pe);
    gemm_qkv_tc<<<dim3(6, 784), 256>>>(wqkv);
    attn_tc<<<BNW * 8, 128>>>(out);
    gemm_out_tc<<<dim3(2, 784), 256>>>(wout, bout);
    scatter_kernel<<<dim3(56, 8, 32), 256>>>(out);
}

// round 9
// speedup vs baseline: 1.1612x; 1.0895x over previous
#include <cuda_runtime.h>
#include <cstdint>

// ---------------- problem constants ----------------
#define B_      32
#define PP      49
#define NW      64
#define BNW     2048
#define MTOK    100352                 // BNW*49
#define QS      25690112               // BNW*8*49*32
#define OUT_ELEMS 25690112

#define NEG_INF __int_as_float(0xff800000)

// ---------------- scratch ----------------
__device__ float g_xw[(size_t)MTOK * 256];
__device__ float g_qkv[(size_t)3 * QS];
__device__ float g_oattn[(size_t)MTOK * 256];
__device__ float g_otok[(size_t)MTOK * 256];
__device__ float g_mask[NW * PP * PP];

// ---------------- tf32 helpers ----------------
__device__ __forceinline__ unsigned f2tf(float f) {
    unsigned u; asm("cvt.rna.tf32.f32 %0, %1;" : "=r"(u) : "f"(f)); return u;
}
// D += A(16x8)*B(8x8) tf32, f32 accum. g=lane>>2, t=lane&3.
__device__ __forceinline__ void mma_tf32(float* c, const unsigned* a, const unsigned* b) {
    asm volatile("mma.sync.aligned.m16n8k8.row.col.f32.tf32.tf32.f32 "
        "{%0,%1,%2,%3}, {%4,%5,%6,%7}, {%8,%9}, {%0,%1,%2,%3};"
        : "+f"(c[0]), "+f"(c[1]), "+f"(c[2]), "+f"(c[3])
        : "r"(a[0]), "r"(a[1]), "r"(a[2]), "r"(a[3]), "r"(b[0]), "r"(b[1]));
}

// ---------------- kernel 1: gather + roll(-3) + window permute ----------------
__global__ void gather_kernel(const float* __restrict__ x) {
    __shared__ float s[32 * 57];
    int xsrow = blockIdx.x;
    int c0 = blockIdx.y * 32;
    int b = blockIdx.z;
    int r = xsrow + 3; if (r >= 56) r -= 56;
    const float* xb = x + ((size_t)(b * 256 + c0) * 3136) + r * 56;
    for (int i = threadIdx.x; i < 32 * 56; i += blockDim.x) {
        int c = i / 56, col = i - c * 56;
        s[c * 57 + col] = xb[(size_t)c * 3136 + col];
    }
    __syncthreads();
    int wi = xsrow / 7, pi = xsrow - wi * 7;
    for (int j = threadIdx.x; j < 32 * 56; j += blockDim.x) {
        int cw = j & 31, pos = j >> 5;
        int wj = pos / 7, pj = pos - wj * 7;
        int col = pos + 3; if (col >= 56) col -= 56;
        int token = (b * 64 + wi * 8 + wj) * 49 + pi * 7 + pj;
        g_xw[(size_t)token * 256 + c0 + cw] = s[cw * 57 + col];
    }
}

// ---------------- kernel 2: mask ----------------
__global__ void mask_kernel(const float* __restrict__ pe) {
    int n = blockIdx.x;
    for (int e = threadIdx.x; e < 2401; e += blockDim.x) {
        int i = e / 49, j = e - i * 49;
        int i7 = i % 7, j7 = j % 7;
        int r0 = j / 7 - i / 7 + 6;
        int r1 = j7 - i7 + 6;
        float v = pe[r0 * 13 + r1];
        if (n >= 56 && ((i >= 28) != (j >= 28))) v = NEG_INF;
        if ((n == 55 || n == 63) && ((i7 >= 4) != (j7 >= 4))) v = NEG_INF;
        g_mask[n * 2401 + e] = v;
    }
}

// ---------------- kernel 3: QKV GEMM (tf32, double-buffered, 1 sync/chunk) ----------------
// C[100352,768] = g_xw @ wqkv. BM=128 BN=64 BK=16, 8 warps (4m x 2n), warp 32x32.
__global__ __launch_bounds__(256) void gemm_qkv_tc(const float* __restrict__ wqkv) {
    __shared__ unsigned As[2][128 * 20];   // [buf][row*20 + k]
    __shared__ unsigned Bs[2][64 * 20];    // [buf][col*20 + k]
    int m0 = blockIdx.y * 128;
    int n0 = blockIdx.x * 64;
    int tid = threadIdx.x;
    int lane = tid & 31, wid = tid >> 5;
    int g = lane >> 2, t = lane & 3;
    int wm = (wid & 3) * 32, wn = (wid >> 2) * 32;

    float acc[2][4][4];
#pragma unroll
    for (int mf = 0; mf < 2; mf++)
#pragma unroll
        for (int nf = 0; nf < 4; nf++)
#pragma unroll
            for (int v = 0; v < 4; v++) acc[mf][nf][v] = 0.f;

    int arow = tid >> 2, ac4 = (tid & 3) * 4;
    int bkk = tid >> 4, bnn = (tid & 15) * 4;
    const float* Ab = g_xw + (size_t)m0 * 256;

    float4 ra0 = *(const float4*)(Ab + (size_t)arow * 256 + ac4);
    float4 ra1 = *(const float4*)(Ab + (size_t)(arow + 64) * 256 + ac4);
    float4 rb  = *(const float4*)(wqkv + (size_t)bkk * 768 + n0 + bnn);

    // write stage 0
    {
        unsigned* ap = &As[0][arow * 20 + ac4];
        ap[0] = f2tf(ra0.x); ap[1] = f2tf(ra0.y); ap[2] = f2tf(ra0.z); ap[3] = f2tf(ra0.w);
        ap = &As[0][(arow + 64) * 20 + ac4];
        ap[0] = f2tf(ra1.x); ap[1] = f2tf(ra1.y); ap[2] = f2tf(ra1.z); ap[3] = f2tf(ra1.w);
        Bs[0][(bnn + 0) * 20 + bkk] = f2tf(rb.x);
        Bs[0][(bnn + 1) * 20 + bkk] = f2tf(rb.y);
        Bs[0][(bnn + 2) * 20 + bkk] = f2tf(rb.z);
        Bs[0][(bnn + 3) * 20 + bkk] = f2tf(rb.w);
    }
    __syncthreads();

    for (int kt = 0; kt < 16; kt++) {
        int buf = kt & 1;
        if (kt < 15) {
            int k0 = (kt + 1) * 16;
            ra0 = *(const float4*)(Ab + (size_t)arow * 256 + k0 + ac4);
            ra1 = *(const float4*)(Ab + (size_t)(arow + 64) * 256 + k0 + ac4);
            rb  = *(const float4*)(wqkv + (size_t)(k0 + bkk) * 768 + n0 + bnn);
        }
#pragma unroll
        for (int kf = 0; kf < 2; kf++) {
            unsigned a[2][4], b[4][2];
#pragma unroll
            for (int mf = 0; mf < 2; mf++) {
                int base = (wm + mf * 16 + g) * 20 + kf * 8 + t;
                a[mf][0] = As[buf][base];
                a[mf][1] = As[buf][base + 8 * 20];
                a[mf][2] = As[buf][base + 4];
                a[mf][3] = As[buf][base + 8 * 20 + 4];
            }
#pragma unroll
            for (int nf = 0; nf < 4; nf++) {
                int bb = (wn + nf * 8 + g) * 20 + kf * 8 + t;
                b[nf][0] = Bs[buf][bb];
                b[nf][1] = Bs[buf][bb + 4];
            }
#pragma unroll
            for (int mf = 0; mf < 2; mf++)
#pragma unroll
                for (int nf = 0; nf < 4; nf++)
                    mma_tf32(acc[mf][nf], a[mf], b[nf]);
        }
        if (kt < 15) {
            int nb = buf ^ 1;
            unsigned* ap = &As[nb][arow * 20 + ac4];
            ap[0] = f2tf(ra0.x); ap[1] = f2tf(ra0.y); ap[2] = f2tf(ra0.z); ap[3] = f2tf(ra0.w);
            ap = &As[nb][(arow + 64) * 20 + ac4];
            ap[0] = f2tf(ra1.x); ap[1] = f2tf(ra1.y); ap[2] = f2tf(ra1.z); ap[3] = f2tf(ra1.w);
            Bs[nb][(bnn + 0) * 20 + bkk] = f2tf(rb.x);
            Bs[nb][(bnn + 1) * 20 + bkk] = f2tf(rb.y);
            Bs[nb][(bnn + 2) * 20 + bkk] = f2tf(rb.z);
            Bs[nb][(bnn + 3) * 20 + bkk] = f2tf(rb.w);
            __syncthreads();
        }
    }

    int mat = n0 >> 8;   // BN=64 tile never straddles a 256 boundary
    float* dst = g_qkv + (size_t)mat * QS;
#pragma unroll
    for (int mf = 0; mf < 2; mf++) {
        int row0 = m0 + wm + mf * 16 + g;
        int bn0 = row0 / 49, tk0 = row0 - bn0 * 49;
        int row1 = row0 + 8;
        int bn1 = row1 / 49, tk1 = row1 - bn1 * 49;
#pragma unroll
        for (int nf = 0; nf < 4; nf++) {
            int ncol = (n0 + wn + nf * 8 + 2 * t) & 255;
            int head = ncol >> 5, dh = ncol & 31;
            *(float2*)&dst[(size_t)((bn0 * 8 + head) * 49 + tk0) * 32 + dh] =
                make_float2(acc[mf][nf][0], acc[mf][nf][1]);
            *(float2*)&dst[(size_t)((bn1 * 8 + head) * 49 + tk1) * 32 + dh] =
                make_float2(acc[mf][nf][2], acc[mf][nf][3]);
        }
    }
}

// ---------------- kernel 4: attention (tf32 MMA) ----------------
__global__ __launch_bounds__(128, 9) void attn_tc(float* __restrict__ dout) {
    __shared__ unsigned SBuf[4320];        // Qs[64*36] | Ks[56*36]; Ps[64*60] aliases
    __shared__ unsigned Vt[32 * 60];
    unsigned* Qs = SBuf;
    unsigned* Ks = SBuf + 64 * 36;
    unsigned* Ps = SBuf;

    int bn = blockIdx.x >> 3, h = blockIdx.x & 7, n = bn & 63;
    int tid = threadIdx.x, lane = tid & 31, w = tid >> 5;
    int g = lane >> 2, t = lane & 3;

    const float* qg = g_qkv + (size_t)((bn * 8 + h) * 49) * 32;
    const float* kg = qg + (size_t)QS;
    const float* vg = qg + (size_t)2 * QS;

    for (int i = tid; i < 2712; i += 128) {
        if (i < 540) Qs[49 * 36 + i] = 0;
        else if (i < 792) Ks[49 * 36 + (i - 540)] = 0;
        else Vt[i - 792] = 0;
    }
    __syncthreads();
    for (int i4 = tid; i4 < 392; i4 += 128) {
        int tk = i4 >> 3, d4 = (i4 & 7) * 4;
        float4 q = *(const float4*)(qg + tk * 32 + d4);
        float4 k = *(const float4*)(kg + tk * 32 + d4);
        float4 v = *(const float4*)(vg + tk * 32 + d4);
        unsigned* qp = &Qs[tk * 36 + d4];
        qp[0] = f2tf(q.x); qp[1] = f2tf(q.y); qp[2] = f2tf(q.z); qp[3] = f2tf(q.w);
        unsigned* kp = &Ks[tk * 36 + d4];
        kp[0] = f2tf(k.x); kp[1] = f2tf(k.y); kp[2] = f2tf(k.z); kp[3] = f2tf(k.w);
        Vt[(d4 + 0) * 60 + tk] = f2tf(v.x);
        Vt[(d4 + 1) * 60 + tk] = f2tf(v.y);
        Vt[(d4 + 2) * 60 + tk] = f2tf(v.z);
        Vt[(d4 + 3) * 60 + tk] = f2tf(v.w);
    }
    __syncthreads();

    float s[7][4];
#pragma unroll
    for (int nf = 0; nf < 7; nf++)
#pragma unroll
        for (int v = 0; v < 4; v++) s[nf][v] = 0.f;
#pragma unroll
    for (int kf = 0; kf < 4; kf++) {
        unsigned a[4];
        int base = (w * 16 + g) * 36 + kf * 8 + t;
        a[0] = Qs[base]; a[1] = Qs[base + 8 * 36];
        a[2] = Qs[base + 4]; a[3] = Qs[base + 8 * 36 + 4];
#pragma unroll
        for (int nf = 0; nf < 7; nf++) {
            unsigned b[2];
            int bb = (nf * 8 + g) * 36 + kf * 8 + t;
            b[0] = Ks[bb]; b[1] = Ks[bb + 4];
            mma_tf32(s[nf], a, b);
        }
    }

    const float scale = 0.17677669529663687f;
    const float* mk = g_mask + n * 2401;
    int row0 = w * 16 + g, row1 = row0 + 8;
#pragma unroll
    for (int nf = 0; nf < 7; nf++) {
        int c0 = nf * 8 + 2 * t, c1 = c0 + 1;
        float m00 = (c0 < 49) ? ((row0 < 49) ? __ldg(mk + row0 * 49 + c0) : 0.f) : NEG_INF;
        float m01 = (c1 < 49) ? ((row0 < 49) ? __ldg(mk + row0 * 49 + c1) : 0.f) : NEG_INF;
        float m10 = (c0 < 49) ? ((row1 < 49) ? __ldg(mk + row1 * 49 + c0) : 0.f) : NEG_INF;
        float m11 = (c1 < 49) ? ((row1 < 49) ? __ldg(mk + row1 * 49 + c1) : 0.f) : NEG_INF;
        s[nf][0] = s[nf][0] * scale + m00;
        s[nf][1] = s[nf][1] * scale + m01;
        s[nf][2] = s[nf][2] * scale + m10;
        s[nf][3] = s[nf][3] * scale + m11;
    }

    float mx0 = NEG_INF, mx1 = NEG_INF;
#pragma unroll
    for (int nf = 0; nf < 7; nf++) {
        mx0 = fmaxf(mx0, fmaxf(s[nf][0], s[nf][1]));
        mx1 = fmaxf(mx1, fmaxf(s[nf][2], s[nf][3]));
    }
    mx0 = fmaxf(mx0, __shfl_xor_sync(0xffffffffu, mx0, 1));
    mx0 = fmaxf(mx0, __shfl_xor_sync(0xffffffffu, mx0, 2));
    mx1 = fmaxf(mx1, __shfl_xor_sync(0xffffffffu, mx1, 1));
    mx1 = fmaxf(mx1, __shfl_xor_sync(0xffffffffu, mx1, 2));
    float sm0 = 0.f, sm1 = 0.f;
#pragma unroll
    for (int nf = 0; nf < 7; nf++) {
        s[nf][0] = __expf(s[nf][0] - mx0);
        s[nf][1] = __expf(s[nf][1] - mx0);
        s[nf][2] = __expf(s[nf][2] - mx1);
        s[nf][3] = __expf(s[nf][3] - mx1);
        sm0 += s[nf][0] + s[nf][1];
        sm1 += s[nf][2] + s[nf][3];
    }
    sm0 += __shfl_xor_sync(0xffffffffu, sm0, 1);
    sm0 += __shfl_xor_sync(0xffffffffu, sm0, 2);
    sm1 += __shfl_xor_sync(0xffffffffu, sm1, 1);
    sm1 += __shfl_xor_sync(0xffffffffu, sm1, 2);
    float inv0 = 1.f / sm0, inv1 = 1.f / sm1;
#pragma unroll
    for (int nf = 0; nf < 7; nf++) {
        s[nf][0] *= inv0; s[nf][1] *= inv0;
        s[nf][2] *= inv1; s[nf][3] *= inv1;
    }

    __syncthreads();

    float* ao = dout + (size_t)OUT_ELEMS + (size_t)((bn * 8 + h) * 49) * 49;
#pragma unroll
    for (int nf = 0; nf < 7; nf++) {
        int c0 = nf * 8 + 2 * t;
        if (row0 < 49) {
            if (c0 < 49) ao[row0 * 49 + c0] = s[nf][0];
            if (c0 + 1 < 49) ao[row0 * 49 + c0 + 1] = s[nf][1];
        }
        if (row1 < 49) {
            if (c0 < 49) ao[row1 * 49 + c0] = s[nf][2];
            if (c0 + 1 < 49) ao[row1 * 49 + c0 + 1] = s[nf][3];
        }
        *(uint2*)&Ps[row0 * 60 + c0] = make_uint2(f2tf(s[nf][0]), f2tf(s[nf][1]));
        *(uint2*)&Ps[row1 * 60 + c0] = make_uint2(f2tf(s[nf][2]), f2tf(s[nf][3]));
    }
    __syncthreads();

    float o[4][4];
#pragma unroll
    for (int nf = 0; nf < 4; nf++)
#pragma unroll
        for (int v = 0; v < 4; v++) o[nf][v] = 0.f;
#pragma unroll
    for (int kf = 0; kf < 7; kf++) {
        unsigned a[4];
        int base = (w * 16 + g) * 60 + kf * 8 + t;
        a[0] = Ps[base]; a[1] = Ps[base + 8 * 60];
        a[2] = Ps[base + 4]; a[3] = Ps[base + 8 * 60 + 4];
#pragma unroll
        for (int nf = 0; nf < 4; nf++) {
            unsigned b[2];
            int bb = (nf * 8 + g) * 60 + kf * 8 + t;
            b[0] = Vt[bb]; b[1] = Vt[bb + 4];
            mma_tf32(o[nf], a, b);
        }
    }
#pragma unroll
    for (int nf = 0; nf < 4; nf++) {
        int col = nf * 8 + 2 * t;
        if (row0 < 49)
            *(float2*)&g_oattn[((size_t)(bn * 49) + row0) * 256 + h * 32 + col] =
                make_float2(o[nf][0], o[nf][1]);
        if (row1 < 49)
            *(float2*)&g_oattn[((size_t)(bn * 49) + row1) * 256 + h * 32 + col] =
                make_float2(o[nf][2], o[nf][3]);
    }
}

// ---------------- kernel 5: output GEMM (tf32, double-buffered) + bias ----------------
__global__ __launch_bounds__(256) void gemm_out_tc(const float* __restrict__ wout,
                                                   const float* __restrict__ bout) {
    __shared__ unsigned As[2][128 * 20];
    __shared__ unsigned Bs[2][64 * 20];
    int m0 = blockIdx.y * 128;
    int n0 = blockIdx.x * 64;
    int tid = threadIdx.x;
    int lane = tid & 31, wid = tid >> 5;
    int g = lane >> 2, t = lane & 3;
    int wm = (wid & 3) * 32, wn = (wid >> 2) * 32;

    float acc[2][4][4];
#pragma unroll
    for (int mf = 0; mf < 2; mf++)
#pragma unroll
        for (int nf = 0; nf < 4; nf++)
#pragma unroll
            for (int v = 0; v < 4; v++) acc[mf][nf][v] = 0.f;

    int arow = tid >> 2, ac4 = (tid & 3) * 4;
    int bkk = tid >> 4, bnn = (tid & 15) * 4;
    const float* Ab = g_oattn + (size_t)m0 * 256;

    float4 ra0 = *(const float4*)(Ab + (size_t)arow * 256 + ac4);
    float4 ra1 = *(const float4*)(Ab + (size_t)(arow + 64) * 256 + ac4);
    float4 rb  = *(const float4*)(wout + (size_t)bkk * 256 + n0 + bnn);

    {
        unsigned* ap = &As[0][arow * 20 + ac4];
        ap[0] = f2tf(ra0.x); ap[1] = f2tf(ra0.y); ap[2] = f2tf(ra0.z); ap[3] = f2tf(ra0.w);
        ap = &As[0][(arow + 64) * 20 + ac4];
        ap[0] = f2tf(ra1.x); ap[1] = f2tf(ra1.y); ap[2] = f2tf(ra1.z); ap[3] = f2tf(ra1.w);
        Bs[0][(bnn + 0) * 20 + bkk] = f2tf(rb.x);
        Bs[0][(bnn + 1) * 20 + bkk] = f2tf(rb.y);
        Bs[0][(bnn + 2) * 20 + bkk] = f2tf(rb.z);
        Bs[0][(bnn + 3) * 20 + bkk] = f2tf(rb.w);
    }
    __syncthreads();

    for (int kt = 0; kt < 16; kt++) {
        int buf = kt & 1;
        if (kt < 15) {
            int k0 = (kt + 1) * 16;
            ra0 = *(const float4*)(Ab + (size_t)arow * 256 + k0 + ac4);
            ra1 = *(const float4*)(Ab + (size_t)(arow + 64) * 256 + k0 + ac4);
            rb  = *(const float4*)(wout + (size_t)(k0 + bkk) * 256 + n0 + bnn);
        }
#pragma unroll
        for (int kf = 0; kf < 2; kf++) {
            unsigned a[2][4], b[4][2];
#pragma unroll
            for (int mf = 0; mf < 2; mf++) {
                int base = (wm + mf * 16 + g) * 20 + kf * 8 + t;
                a[mf][0] = As[buf][base];
                a[mf][1] = As[buf][base + 8 * 20];
                a[mf][2] = As[buf][base + 4];
                a[mf][3] = As[buf][base + 8 * 20 + 4];
            }
#pragma unroll
            for (int nf = 0; nf < 4; nf++) {
                int bb = (wn + nf * 8 + g) * 20 + kf * 8 + t;
                b[nf][0] = Bs[buf][bb];
                b[nf][1] = Bs[buf][bb + 4];
            }
#pragma unroll
            for (int mf = 0; mf < 2; mf++)
#pragma unroll
                for (int nf = 0; nf < 4; nf++)
                    mma_tf32(acc[mf][nf], a[mf], b[nf]);
        }
        if (kt < 15) {
            int nb = buf ^ 1;
            unsigned* ap = &As[nb][arow * 20 + ac4];
            ap[0] = f2tf(ra0.x); ap[1] = f2tf(ra0.y); ap[2] = f2tf(ra0.z); ap[3] = f2tf(ra0.w);
            ap = &As[nb][(arow + 64) * 20 + ac4];
            ap[0] = f2tf(ra1.x); ap[1] = f2tf(ra1.y); ap[2] = f2tf(ra1.z); ap[3] = f2tf(ra1.w);
            Bs[nb][(bnn + 0) * 20 + bkk] = f2tf(rb.x);
            Bs[nb][(bnn + 1) * 20 + bkk] = f2tf(rb.y);
            Bs[nb][(bnn + 2) * 20 + bkk] = f2tf(rb.z);
            Bs[nb][(bnn + 3) * 20 + bkk] = f2tf(rb.w);
            __syncthreads();
        }
    }

#pragma unroll
    for (int mf = 0; mf < 2; mf++) {
        int row0 = m0 + wm + mf * 16 + g;
#pragma unroll
        for (int nf = 0; nf < 4; nf++) {
            int ncol = n0 + wn + nf * 8 + 2 * t;
            float2 bv = *(const float2*)&bout[ncol];
            *(float2*)&g_otok[(size_t)row0 * 256 + ncol] =
                make_float2(acc[mf][nf][0] + bv.x, acc[mf][nf][1] + bv.y);
            *(float2*)&g_otok[(size_t)(row0 + 8) * 256 + ncol] =
                make_float2(acc[mf][nf][2] + bv.x, acc[mf][nf][3] + bv.y);
        }
    }
}

// ---------------- kernel 6: scatter ----------------
__global__ void scatter_kernel(float* __restrict__ out) {
    __shared__ float s[32 * 57];
    int xsrow = blockIdx.x;
    int c0 = blockIdx.y * 32;
    int b = blockIdx.z;
    int wi = xsrow / 7, pi = xsrow - wi * 7;
    for (int j = threadIdx.x; j < 32 * 56; j += blockDim.x) {
        int cw = j & 31, pos = j >> 5;
        int wj = pos / 7, pj = pos - wj * 7;
        int col = pos + 3; if (col >= 56) col -= 56;
        int token = (b * 64 + wi * 8 + wj) * 49 + pi * 7 + pj;
        s[cw * 57 + col] = g_otok[(size_t)token * 256 + c0 + cw];
    }
    __syncthreads();
    int r = xsrow + 3; if (r >= 56) r -= 56;
    float* ob = out + ((size_t)(b * 256 + c0) * 3136) + r * 56;
    for (int i = threadIdx.x; i < 32 * 56; i += blockDim.x) {
        int c = i / 56, col = i - c * 56;
        ob[(size_t)c * 3136 + col] = s[c * 57 + col];
    }
}

// ---------------- launch ----------------
extern "C" void kernel_launch(void* const* d_in, const int* in_sizes, int n_in,
                              void* d_out, int out_size) {
    const float* x    = (const float*)d_in[0];
    const float* pe   = (const float*)d_in[1];
    const float* wqkv = (const float*)d_in[2];
    const float* wout = (const float*)d_in[3];
    const float* bout = (const float*)d_in[4];
    float* out = (float*)d_out;

    gather_kernel<<<dim3(56, 8, 32), 256>>>(x);
    mask_kernel<<<64, 256>>>(pe);
    gemm_qkv_tc<<<dim3(12, 784), 256>>>(wqkv);
    attn_tc<<<BNW * 8, 128>>>(out);
    gemm_out_tc<<<dim3(4, 784), 256>>>(wout, bout);
    scatter_kernel<<<dim3(56, 8, 32), 256>>>(out);
}

// round 10
// speedup vs baseline: 1.6769x; 1.4442x over previous
#include <cuda_runtime.h>
#include <cuda_fp16.h>
#include <cstdint>

// ---------------- problem constants ----------------
#define B_      32
#define PP      49
#define NW      64
#define BNW     2048
#define MTOK    100352                 // BNW*49
#define QS      25690112               // halves per q/k/v tensor
#define QSW     (QS/2)                 // words per q/k/v tensor
#define OUT_ELEMS 25690112

#define NEG_INF __int_as_float(0xff800000)

// ---------------- scratch (half2-packed words) ----------------
__device__ __align__(16) unsigned g_xw[(size_t)MTOK * 128];     // [token][kw]
__device__ __align__(16) unsigned g_qkv[(size_t)3 * QSW];       // q|k|v, [bn,h,t][dhw]
__device__ __align__(16) unsigned g_oattn[(size_t)MTOK * 128];  // [token][kw]
__device__ __align__(16) unsigned h_wqkv[768 * 128];            // [n][kw]
__device__ __align__(16) unsigned h_wout[256 * 128];            // [n][kw]
__device__ float g_otok[(size_t)MTOK * 256];
__device__ float g_mask[NW * PP * PP];

// ---------------- helpers ----------------
__device__ __forceinline__ unsigned pack2(float a, float b) {
    __half2 h = __floats2half2_rn(a, b);
    return *(unsigned*)&h;
}
// D += A(16x16)*B(16x8) fp16, f32 accum. g=lane>>2, t=lane&3.
// a0={A[g][2t,2t+1]} a1={A[g+8][..]} a2={A[g][2t+8,2t+9]} a3={A[g+8][..]}
// b0={B[2t,2t+1][g]} b1={B[2t+8,2t+9][g]}   c: C[g][2t],C[g][2t+1],C[g+8][2t],C[g+8][2t+1]
__device__ __forceinline__ void mma_f16(float* c, const unsigned* a, const unsigned* b) {
    asm volatile("mma.sync.aligned.m16n8k16.row.col.f32.f16.f16.f32 "
        "{%0,%1,%2,%3}, {%4,%5,%6,%7}, {%8,%9}, {%0,%1,%2,%3};"
        : "+f"(c[0]), "+f"(c[1]), "+f"(c[2]), "+f"(c[3])
        : "r"(a[0]), "r"(a[1]), "r"(a[2]), "r"(a[3]), "r"(b[0]), "r"(b[1]));
}

// ---------------- kernel 1: gather + roll(-3) + window permute (fp16 out) ----------------
__global__ void gather_kernel(const float* __restrict__ x) {
    __shared__ float s[32 * 57];
    int xsrow = blockIdx.x;
    int c0 = blockIdx.y * 32;
    int b = blockIdx.z;
    int r = xsrow + 3; if (r >= 56) r -= 56;
    const float* xb = x + ((size_t)(b * 256 + c0) * 3136) + r * 56;
    for (int i = threadIdx.x; i < 32 * 56; i += blockDim.x) {
        int c = i / 56, col = i - c * 56;
        s[c * 57 + col] = xb[(size_t)c * 3136 + col];
    }
    __syncthreads();
    __half* gx = (__half*)g_xw;
    int wi = xsrow / 7, pi = xsrow - wi * 7;
    for (int j = threadIdx.x; j < 32 * 56; j += blockDim.x) {
        int cw = j & 31, pos = j >> 5;
        int wj = pos / 7, pj = pos - wj * 7;
        int col = pos + 3; if (col >= 56) col -= 56;
        int token = (b * 64 + wi * 8 + wj) * 49 + pi * 7 + pj;
        gx[(size_t)token * 256 + c0 + cw] = __float2half_rn(s[cw * 57 + col]);
    }
}

// ---------------- kernel 1b: pre-pack weights to half2 [n][kw] ----------------
__global__ void convert_w(const float* __restrict__ wqkv, const float* __restrict__ wout) {
    int i = blockIdx.x * 256 + threadIdx.x;
    if (i < 768 * 128) {
        int n = i >> 7, kw = i & 127;
        h_wqkv[i] = pack2(wqkv[(size_t)(2 * kw) * 768 + n], wqkv[(size_t)(2 * kw + 1) * 768 + n]);
    }
    if (i < 256 * 128) {
        int n = i >> 7, kw = i & 127;
        h_wout[i] = pack2(wout[(size_t)(2 * kw) * 256 + n], wout[(size_t)(2 * kw + 1) * 256 + n]);
    }
}

// ---------------- kernel 2: mask ----------------
__global__ void mask_kernel(const float* __restrict__ pe) {
    int n = blockIdx.x;
    for (int e = threadIdx.x; e < 2401; e += blockDim.x) {
        int i = e / 49, j = e - i * 49;
        int i7 = i % 7, j7 = j % 7;
        int r0 = j / 7 - i / 7 + 6;
        int r1 = j7 - i7 + 6;
        float v = pe[r0 * 13 + r1];
        if (n >= 56 && ((i >= 28) != (j >= 28))) v = NEG_INF;
        if ((n == 55 || n == 63) && ((i7 >= 4) != (j7 >= 4))) v = NEG_INF;
        g_mask[n * 2401 + e] = v;
    }
}

// ================= fp16 GEMM core: BM=128 BN=64 BK=16, 8 warps 4m x 2n =================
// smem: [row][8 kw words], stride 12 (conflict-free: g*12 mod 32 = distinct mult of 4)

// ---------------- kernel 3: QKV GEMM ----------------
__global__ __launch_bounds__(256) void gemm_qkv_f16() {
    __shared__ __align__(16) unsigned As[2][128 * 12];
    __shared__ __align__(16) unsigned Bs[2][64 * 12];
    int m0 = blockIdx.y * 128;
    int n0 = blockIdx.x * 64;
    int tid = threadIdx.x;
    int lane = tid & 31, wid = tid >> 5;
    int g = lane >> 2, t = lane & 3;
    int wm = (wid & 3) * 32, wn = (wid >> 2) * 32;

    float acc[2][4][4];
#pragma unroll
    for (int mf = 0; mf < 2; mf++)
#pragma unroll
        for (int nf = 0; nf < 4; nf++)
#pragma unroll
            for (int v = 0; v < 4; v++) acc[mf][nf][v] = 0.f;

    int arow = tid >> 1, apart = tid & 1;         // A: row, 4-word half
    int bn_ = tid >> 2, bw2 = (tid & 3) * 2;      // B: col, 2-word slot
    const uint4* Aw = (const uint4*)(g_xw + (size_t)(m0 + arow) * 128) + apart;
    const uint2* Bw = (const uint2*)(h_wqkv + (size_t)(n0 + bn_) * 128 + bw2);

    uint4 rA = Aw[0];
    uint2 rB = Bw[0];
    *(uint4*)&As[0][arow * 12 + apart * 4] = rA;
    *(uint2*)&Bs[0][bn_ * 12 + bw2] = rB;
    __syncthreads();

    for (int kc = 0; kc < 16; kc++) {
        int buf = kc & 1;
        if (kc < 15) {
            rA = Aw[(kc + 1) * 2];                 // +16 halves = 2 uint4 per chunk
            rB = *(const uint2*)((const unsigned*)Bw + (kc + 1) * 8);
        }
        unsigned a[2][4], b[4][2];
#pragma unroll
        for (int mf = 0; mf < 2; mf++) {
            int base = (wm + mf * 16 + g) * 12 + t;
            a[mf][0] = As[buf][base];
            a[mf][1] = As[buf][base + 8 * 12];
            a[mf][2] = As[buf][base + 4];
            a[mf][3] = As[buf][base + 8 * 12 + 4];
        }
#pragma unroll
        for (int nf = 0; nf < 4; nf++) {
            int bb = (wn + nf * 8 + g) * 12 + t;
            b[nf][0] = Bs[buf][bb];
            b[nf][1] = Bs[buf][bb + 4];
        }
#pragma unroll
        for (int mf = 0; mf < 2; mf++)
#pragma unroll
            for (int nf = 0; nf < 4; nf++)
                mma_f16(acc[mf][nf], a[mf], b[nf]);
        if (kc < 15) {
            int nb = buf ^ 1;
            *(uint4*)&As[nb][arow * 12 + apart * 4] = rA;
            *(uint2*)&Bs[nb][bn_ * 12 + bw2] = rB;
            __syncthreads();
        }
    }

    int mat = n0 >> 8;
    unsigned* dst = g_qkv + (size_t)mat * QSW;
#pragma unroll
    for (int mf = 0; mf < 2; mf++) {
        int row0 = m0 + wm + mf * 16 + g;
        int bnw0 = row0 / 49, tk0 = row0 - bnw0 * 49;
        int row1 = row0 + 8;
        int bnw1 = row1 / 49, tk1 = row1 - bnw1 * 49;
#pragma unroll
        for (int nf = 0; nf < 4; nf++) {
            int ncol = (n0 + wn + nf * 8 + 2 * t) & 255;
            int head = ncol >> 5, dhw = (ncol & 31) >> 1;
            dst[(size_t)((bnw0 * 8 + head) * 49 + tk0) * 16 + dhw] =
                pack2(acc[mf][nf][0], acc[mf][nf][1]);
            dst[(size_t)((bnw1 * 8 + head) * 49 + tk1) * 16 + dhw] =
                pack2(acc[mf][nf][2], acc[mf][nf][3]);
        }
    }
}

// ---------------- kernel 4: attention (fp16 MMA) ----------------
// Qs[64x20] | Ks[56x20] in SB (Ps[64x36] aliases); Vt[32x36].
__global__ __launch_bounds__(128, 9) void attn_f16(float* __restrict__ dout) {
    __shared__ unsigned SB[2400];
    __shared__ unsigned Vt[1152];
    unsigned* Qs = SB;
    unsigned* Ks = SB + 1280;
    unsigned* Ps = SB;

    int bn = blockIdx.x >> 3, h = blockIdx.x & 7, n = bn & 63;
    int tid = threadIdx.x, lane = tid & 31, w = tid >> 5;
    int g = lane >> 2, t = lane & 3;

    const unsigned* qw = g_qkv + (size_t)((bn * 8 + h) * 49) * 16;
    const unsigned* kw_ = qw + QSW;
    const unsigned* vw = qw + (size_t)2 * QSW;

    // zero pads: Qs rows 49..63 (300 w), Ks rows 49..55 (140 w), Vt all (1152 w)
    for (int i = tid; i < 1592; i += 128) {
        if (i < 300) Qs[980 + i] = 0;
        else if (i < 440) Ks[980 + (i - 300)] = 0;
        else Vt[i - 440] = 0;
    }
    __syncthreads();
    for (int i = tid; i < 784; i += 128) {
        int tk = i >> 4, kwi = i & 15;
        Qs[tk * 20 + kwi] = qw[i];
        Ks[tk * 20 + kwi] = kw_[i];
    }
    for (int i = tid; i < 400; i += 128) {
        int m = i >> 4, dw = i & 15;
        unsigned v0 = vw[(2 * m) * 16 + dw];
        unsigned v1 = (2 * m + 1 < 49) ? vw[(2 * m + 1) * 16 + dw] : 0u;
        __half2 va = *(__half2*)&v0, vb = *(__half2*)&v1;
        __half2 lo = __lows2half2(va, vb);
        __half2 hi = __highs2half2(va, vb);
        Vt[(2 * dw) * 36 + m] = *(unsigned*)&lo;
        Vt[(2 * dw + 1) * 36 + m] = *(unsigned*)&hi;
    }
    __syncthreads();

    // S = Q @ K^T  (2 k16 steps over dh=32)
    float s[7][4];
#pragma unroll
    for (int nf = 0; nf < 7; nf++)
#pragma unroll
        for (int v = 0; v < 4; v++) s[nf][v] = 0.f;
#pragma unroll
    for (int st = 0; st < 2; st++) {
        unsigned a[4];
        int base = (w * 16 + g) * 20 + st * 8 + t;
        a[0] = Qs[base]; a[1] = Qs[base + 8 * 20];
        a[2] = Qs[base + 4]; a[3] = Qs[base + 8 * 20 + 4];
#pragma unroll
        for (int nf = 0; nf < 7; nf++) {
            unsigned b[2];
            int bb = (nf * 8 + g) * 20 + st * 8 + t;
            b[0] = Ks[bb]; b[1] = Ks[bb + 4];
            mma_f16(s[nf], a, b);
        }
    }

    const float scale = 0.17677669529663687f;
    const float* mk = g_mask + n * 2401;
    int row0 = w * 16 + g, row1 = row0 + 8;
#pragma unroll
    for (int nf = 0; nf < 7; nf++) {
        int c0 = nf * 8 + 2 * t, c1 = c0 + 1;
        float m00 = (c0 < 49) ? ((row0 < 49) ? __ldg(mk + row0 * 49 + c0) : 0.f) : NEG_INF;
        float m01 = (c1 < 49) ? ((row0 < 49) ? __ldg(mk + row0 * 49 + c1) : 0.f) : NEG_INF;
        float m10 = (c0 < 49) ? ((row1 < 49) ? __ldg(mk + row1 * 49 + c0) : 0.f) : NEG_INF;
        float m11 = (c1 < 49) ? ((row1 < 49) ? __ldg(mk + row1 * 49 + c1) : 0.f) : NEG_INF;
        s[nf][0] = s[nf][0] * scale + m00;
        s[nf][1] = s[nf][1] * scale + m01;
        s[nf][2] = s[nf][2] * scale + m10;
        s[nf][3] = s[nf][3] * scale + m11;
    }

    float mx0 = NEG_INF, mx1 = NEG_INF;
#pragma unroll
    for (int nf = 0; nf < 7; nf++) {
        mx0 = fmaxf(mx0, fmaxf(s[nf][0], s[nf][1]));
        mx1 = fmaxf(mx1, fmaxf(s[nf][2], s[nf][3]));
    }
    mx0 = fmaxf(mx0, __shfl_xor_sync(0xffffffffu, mx0, 1));
    mx0 = fmaxf(mx0, __shfl_xor_sync(0xffffffffu, mx0, 2));
    mx1 = fmaxf(mx1, __shfl_xor_sync(0xffffffffu, mx1, 1));
    mx1 = fmaxf(mx1, __shfl_xor_sync(0xffffffffu, mx1, 2));
    float sm0 = 0.f, sm1 = 0.f;
#pragma unroll
    for (int nf = 0; nf < 7; nf++) {
        s[nf][0] = __expf(s[nf][0] - mx0);
        s[nf][1] = __expf(s[nf][1] - mx0);
        s[nf][2] = __expf(s[nf][2] - mx1);
        s[nf][3] = __expf(s[nf][3] - mx1);
        sm0 += s[nf][0] + s[nf][1];
        sm1 += s[nf][2] + s[nf][3];
    }
    sm0 += __shfl_xor_sync(0xffffffffu, sm0, 1);
    sm0 += __shfl_xor_sync(0xffffffffu, sm0, 2);
    sm1 += __shfl_xor_sync(0xffffffffu, sm1, 1);
    sm1 += __shfl_xor_sync(0xffffffffu, sm1, 2);
    float inv0 = 1.f / sm0, inv1 = 1.f / sm1;
#pragma unroll
    for (int nf = 0; nf < 7; nf++) {
        s[nf][0] *= inv0; s[nf][1] *= inv0;
        s[nf][2] *= inv1; s[nf][3] *= inv1;
    }

    __syncthreads();   // everyone done reading Qs/Ks before Ps overwrites

    float* ao = dout + (size_t)OUT_ELEMS + (size_t)((bn * 8 + h) * 49) * 49;
#pragma unroll
    for (int nf = 0; nf < 7; nf++) {
        int c0 = nf * 8 + 2 * t;
        if (row0 < 49) {
            if (c0 < 49) ao[row0 * 49 + c0] = s[nf][0];
            if (c0 + 1 < 49) ao[row0 * 49 + c0 + 1] = s[nf][1];
        }
        if (row1 < 49) {
            if (c0 < 49) ao[row1 * 49 + c0] = s[nf][2];
            if (c0 + 1 < 49) ao[row1 * 49 + c0 + 1] = s[nf][3];
        }
        Ps[row0 * 36 + nf * 4 + t] = pack2(s[nf][0], s[nf][1]);
        Ps[row1 * 36 + nf * 4 + t] = pack2(s[nf][2], s[nf][3]);
    }
    // zero Ps pad words kw 28..31 (keys 56..63)
    for (int i = tid; i < 256; i += 128)
        Ps[(i >> 2) * 36 + 28 + (i & 3)] = 0;
    __syncthreads();

    // O = P @ V  (4 k16 steps over keys)
    float o[4][4];
#pragma unroll
    for (int nf = 0; nf < 4; nf++)
#pragma unroll
        for (int v = 0; v < 4; v++) o[nf][v] = 0.f;
#pragma unroll
    for (int st = 0; st < 4; st++) {
        unsigned a[4];
        int base = (w * 16 + g) * 36 + st * 8 + t;
        a[0] = Ps[base]; a[1] = Ps[base + 8 * 36];
        a[2] = Ps[base + 4]; a[3] = Ps[base + 8 * 36 + 4];
#pragma unroll
        for (int nf = 0; nf < 4; nf++) {
            unsigned b[2];
            int bb = (nf * 8 + g) * 36 + st * 8 + t;
            b[0] = Vt[bb]; b[1] = Vt[bb + 4];
            mma_f16(o[nf], a, b);
        }
    }
    unsigned* ow = g_oattn;
#pragma unroll
    for (int nf = 0; nf < 4; nf++) {
        int cw = h * 16 + nf * 4 + t;
        if (row0 < 49)
            ow[(size_t)(bn * 49 + row0) * 128 + cw] = pack2(o[nf][0], o[nf][1]);
        if (row1 < 49)
            ow[(size_t)(bn * 49 + row1) * 128 + cw] = pack2(o[nf][2], o[nf][3]);
    }
}

// ---------------- kernel 5: output GEMM + bias ----------------
__global__ __launch_bounds__(256) void gemm_out_f16(const float* __restrict__ bout) {
    __shared__ __align__(16) unsigned As[2][128 * 12];
    __shared__ __align__(16) unsigned Bs[2][64 * 12];
    int m0 = blockIdx.y * 128;
    int n0 = blockIdx.x * 64;
    int tid = threadIdx.x;
    int lane = tid & 31, wid = tid >> 5;
    int g = lane >> 2, t = lane & 3;
    int wm = (wid & 3) * 32, wn = (wid >> 2) * 32;

    float acc[2][4][4];
#pragma unroll
    for (int mf = 0; mf < 2; mf++)
#pragma unroll
        for (int nf = 0; nf < 4; nf++)
#pragma unroll
            for (int v = 0; v < 4; v++) acc[mf][nf][v] = 0.f;

    int arow = tid >> 1, apart = tid & 1;
    int bn_ = tid >> 2, bw2 = (tid & 3) * 2;
    const uint4* Aw = (const uint4*)(g_oattn + (size_t)(m0 + arow) * 128) + apart;
    const uint2* Bw = (const uint2*)(h_wout + (size_t)(n0 + bn_) * 128 + bw2);

    uint4 rA = Aw[0];
    uint2 rB = Bw[0];
    *(uint4*)&As[0][arow * 12 + apart * 4] = rA;
    *(uint2*)&Bs[0][bn_ * 12 + bw2] = rB;
    __syncthreads();

    for (int kc = 0; kc < 16; kc++) {
        int buf = kc & 1;
        if (kc < 15) {
            rA = Aw[(kc + 1) * 2];
            rB = *(const uint2*)((const unsigned*)Bw + (kc + 1) * 8);
        }
        unsigned a[2][4], b[4][2];
#pragma unroll
        for (int mf = 0; mf < 2; mf++) {
            int base = (wm + mf * 16 + g) * 12 + t;
            a[mf][0] = As[buf][base];
            a[mf][1] = As[buf][base + 8 * 12];
            a[mf][2] = As[buf][base + 4];
            a[mf][3] = As[buf][base + 8 * 12 + 4];
        }
#pragma unroll
        for (int nf = 0; nf < 4; nf++) {
            int bb = (wn + nf * 8 + g) * 12 + t;
            b[nf][0] = Bs[buf][bb];
            b[nf][1] = Bs[buf][bb + 4];
        }
#pragma unroll
        for (int mf = 0; mf < 2; mf++)
#pragma unroll
            for (int nf = 0; nf < 4; nf++)
                mma_f16(acc[mf][nf], a[mf], b[nf]);
        if (kc < 15) {
            int nb = buf ^ 1;
            *(uint4*)&As[nb][arow * 12 + apart * 4] = rA;
            *(uint2*)&Bs[nb][bn_ * 12 + bw2] = rB;
            __syncthreads();
        }
    }

#pragma unroll
    for (int mf = 0; mf < 2; mf++) {
        int row0 = m0 + wm + mf * 16 + g;
#pragma unroll
        for (int nf = 0; nf < 4; nf++) {
            int ncol = n0 + wn + nf * 8 + 2 * t;
            float2 bv = *(const float2*)&bout[ncol];
            *(float2*)&g_otok[(size_t)row0 * 256 + ncol] =
                make_float2(acc[mf][nf][0] + bv.x, acc[mf][nf][1] + bv.y);
            *(float2*)&g_otok[(size_t)(row0 + 8) * 256 + ncol] =
                make_float2(acc[mf][nf][2] + bv.x, acc[mf][nf][3] + bv.y);
        }
    }
}

// ---------------- kernel 6: scatter ----------------
__global__ void scatter_kernel(float* __restrict__ out) {
    __shared__ float s[32 * 57];
    int xsrow = blockIdx.x;
    int c0 = blockIdx.y * 32;
    int b = blockIdx.z;
    int wi = xsrow / 7, pi = xsrow - wi * 7;
    for (int j = threadIdx.x; j < 32 * 56; j += blockDim.x) {
        int cw = j & 31, pos = j >> 5;
        int wj = pos / 7, pj = pos - wj * 7;
        int col = pos + 3; if (col >= 56) col -= 56;
        int token = (b * 64 + wi * 8 + wj) * 49 + pi * 7 + pj;
        s[cw * 57 + col] = g_otok[(size_t)token * 256 + c0 + cw];
    }
    __syncthreads();
    int r = xsrow + 3; if (r >= 56) r -= 56;
    float* ob = out + ((size_t)(b * 256 + c0) * 3136) + r * 56;
    for (int i = threadIdx.x; i < 32 * 56; i += blockDim.x) {
        int c = i / 56, col = i - c * 56;
        ob[(size_t)c * 3136 + col] = s[c * 57 + col];
    }
}

// ---------------- launch ----------------
extern "C" void kernel_launch(void* const* d_in, const int* in_sizes, int n_in,
                              void* d_out, int out_size) {
    const float* x    = (const float*)d_in[0];
    const float* pe   = (const float*)d_in[1];
    const float* wqkv = (const float*)d_in[2];
    const float* wout = (const float*)d_in[3];
    const float* bout = (const float*)d_in[4];
    float* out = (float*)d_out;

    gather_kernel<<<dim3(56, 8, 32), 256>>>(x);
    convert_w<<<384, 256>>>(wqkv, wout);
    mask_kernel<<<64, 256>>>(pe);
    gemm_qkv_f16<<<dim3(12, 784), 256>>>();
    attn_f16<<<BNW * 8, 128>>>(out);
    gemm_out_f16<<<dim3(4, 784), 256>>>(bout);
    scatter_kernel<<<dim3(56, 8, 32), 256>>>(out);
}

// round 13
// speedup vs baseline: 1.9825x; 1.1823x over previous
#include <cuda_runtime.h>
#include <cuda_fp16.h>
#include <cstdint>

// ---------------- problem constants ----------------
#define B_      32
#define PP      49
#define NW      64
#define BNW     2048
#define MTOK    100352                 // BNW*49
#define QS      25690112               // halves per q/k/v tensor
#define QSW     (QS/2)                 // words per q/k/v tensor
#define OUT_ELEMS 25690112

#define NEG_INF __int_as_float(0xff800000)

// ---------------- scratch (half2-packed words) ----------------
__device__ __align__(16) unsigned g_xw[(size_t)MTOK * 128];     // [token][kw]
__device__ __align__(16) unsigned g_qkv[(size_t)3 * QSW];       // q|k|v, [bn,h,t][dhw]
__device__ __align__(16) unsigned g_oattn[(size_t)MTOK * 128];  // [token][kw]
__device__ __align__(16) unsigned h_wqkv[768 * 128];            // [n][kw]
__device__ __align__(16) unsigned h_wout[256 * 128];            // [n][kw]
__device__ float g_otok[(size_t)MTOK * 256];
__device__ float g_mask[NW * PP * PP];

// ---------------- helpers ----------------
__device__ __forceinline__ unsigned pack2(float a, float b) {
    __half2 h = __floats2half2_rn(a, b);
    return *(unsigned*)&h;
}
__device__ __forceinline__ void mma_f16(float* c, const unsigned* a, const unsigned* b) {
    asm volatile("mma.sync.aligned.m16n8k16.row.col.f32.f16.f16.f32 "
        "{%0,%1,%2,%3}, {%4,%5,%6,%7}, {%8,%9}, {%0,%1,%2,%3};"
        : "+f"(c[0]), "+f"(c[1]), "+f"(c[2]), "+f"(c[3])
        : "r"(a[0]), "r"(a[1]), "r"(a[2]), "r"(a[3]), "r"(b[0]), "r"(b[1]));
}
__device__ __forceinline__ void cpa16(unsigned saddr, const void* g) {
    asm volatile("cp.async.cg.shared.global [%0], [%1], 16;" :: "r"(saddr), "l"(g) : "memory");
}
#define CP_COMMIT() asm volatile("cp.async.commit_group;" ::: "memory")
#define CP_WAIT1()  asm volatile("cp.async.wait_group 1;" ::: "memory")
#define CP_WAIT0()  asm volatile("cp.async.wait_group 0;" ::: "memory")

// ---------------- kernel 1: gather + roll(-3) + window permute (half2 out) ----------------
__global__ void gather_kernel(const float* __restrict__ x) {
    __shared__ float s[32 * 57];
    int xsrow = blockIdx.x;
    int c0 = blockIdx.y * 32;
    int b = blockIdx.z;
    int r = xsrow + 3; if (r >= 56) r -= 56;
    const float* xb = x + ((size_t)(b * 256 + c0) * 3136) + r * 56;
    for (int i = threadIdx.x; i < 32 * 56; i += blockDim.x) {
        int c = i / 56, col = i - c * 56;
        s[c * 57 + col] = xb[(size_t)c * 3136 + col];
    }
    __syncthreads();
    int wi = xsrow / 7, pi = xsrow - wi * 7;
    for (int j = threadIdx.x; j < 16 * 56; j += blockDim.x) {
        int cp = j & 15, pos = j >> 4;
        int wj = pos / 7, pj = pos - wj * 7;
        int col = pos + 3; if (col >= 56) col -= 56;
        int token = (b * 64 + wi * 8 + wj) * 49 + pi * 7 + pj;
        g_xw[(size_t)token * 128 + (c0 >> 1) + cp] =
            pack2(s[(2 * cp) * 57 + col], s[(2 * cp + 1) * 57 + col]);
    }
}

// ---------------- kernel 1b: pre-pack weights to half2 [n][kw] ----------------
__global__ void convert_w(const float* __restrict__ wqkv, const float* __restrict__ wout) {
    int i = blockIdx.x * 256 + threadIdx.x;
    if (i < 768 * 128) {
        int n = i >> 7, kw = i & 127;
        h_wqkv[i] = pack2(wqkv[(size_t)(2 * kw) * 768 + n], wqkv[(size_t)(2 * kw + 1) * 768 + n]);
    }
    if (i < 256 * 128) {
        int n = i >> 7, kw = i & 127;
        h_wout[i] = pack2(wout[(size_t)(2 * kw) * 256 + n], wout[(size_t)(2 * kw + 1) * 256 + n]);
    }
}

// ---------------- kernel 2: mask ----------------
__global__ void mask_kernel(const float* __restrict__ pe) {
    int n = blockIdx.x;
    for (int e = threadIdx.x; e < 2401; e += blockDim.x) {
        int i = e / 49, j = e - i * 49;
        int i7 = i % 7, j7 = j % 7;
        int r0 = j / 7 - i / 7 + 6;
        int r1 = j7 - i7 + 6;
        float v = pe[r0 * 13 + r1];
        if (n >= 56 && ((i >= 28) != (j >= 28))) v = NEG_INF;
        if ((n == 55 || n == 63) && ((i7 >= 4) != (j7 >= 4))) v = NEG_INF;
        g_mask[n * 2401 + e] = v;
    }
}

// ================= fp16 GEMM, cp.async 3-stage: BM=128 BN=64 BK=16, 8 warps 4m x 2n ==========

// ---------------- kernel 3: QKV GEMM ----------------
__global__ __launch_bounds__(256, 4) void gemm_qkv_f16() {
    __shared__ __align__(16) unsigned As[3][128 * 12];
    __shared__ __align__(16) unsigned Bs[3][64 * 12];
    int m0 = blockIdx.y * 128;
    int n0 = blockIdx.x * 64;
    int tid = threadIdx.x;
    int lane = tid & 31, wid = tid >> 5;
    int g = lane >> 2, t = lane & 3;
    int wm = (wid & 3) * 32, wn = (wid >> 2) * 32;

    float acc[2][4][4];
#pragma unroll
    for (int mf = 0; mf < 2; mf++)
#pragma unroll
        for (int nf = 0; nf < 4; nf++)
#pragma unroll
            for (int v = 0; v < 4; v++) acc[mf][nf][v] = 0.f;

    int arow = tid >> 1, apart = tid & 1;
    const unsigned* Ag = g_xw + (size_t)(m0 + arow) * 128 + apart * 4;
    unsigned aDst0 = (unsigned)__cvta_generic_to_shared(&As[0][arow * 12 + apart * 4]);
    const unsigned* Bg = h_wqkv + (size_t)(n0 + (tid >> 1)) * 128 + apart * 4;
    unsigned bDst0 = (unsigned)__cvta_generic_to_shared(&Bs[0][(tid >> 1) * 12 + apart * 4]);
    const unsigned ASTG = 128 * 12 * 4, BSTG = 64 * 12 * 4;

    auto issue = [&](int s, int buf) {
        cpa16(aDst0 + buf * ASTG, Ag + s * 8);
        if (tid < 128) cpa16(bDst0 + buf * BSTG, Bg + s * 8);
        CP_COMMIT();
    };

    issue(0, 0);
    issue(1, 1);
    for (int s = 0; s < 16; s++) {
        int buf = s % 3;
        if (s == 15) CP_WAIT0(); else CP_WAIT1();   // tail fix: group 15 must be complete
        __syncthreads();
        if (s + 2 < 16) issue(s + 2, (s + 2) % 3);
        unsigned a[2][4], b[4][2];
#pragma unroll
        for (int mf = 0; mf < 2; mf++) {
            int base = (wm + mf * 16 + g) * 12 + t;
            a[mf][0] = As[buf][base];
            a[mf][1] = As[buf][base + 8 * 12];
            a[mf][2] = As[buf][base + 4];
            a[mf][3] = As[buf][base + 8 * 12 + 4];
        }
#pragma unroll
        for (int nf = 0; nf < 4; nf++) {
            int bb = (wn + nf * 8 + g) * 12 + t;
            b[nf][0] = Bs[buf][bb];
            b[nf][1] = Bs[buf][bb + 4];
        }
#pragma unroll
        for (int mf = 0; mf < 2; mf++)
#pragma unroll
            for (int nf = 0; nf < 4; nf++)
                mma_f16(acc[mf][nf], a[mf], b[nf]);
        __syncthreads();
    }

    int mat = n0 >> 8;
    unsigned* dst = g_qkv + (size_t)mat * QSW;
#pragma unroll
    for (int mf = 0; mf < 2; mf++) {
        int row0 = m0 + wm + mf * 16 + g;
        int bnw0 = row0 / 49, tk0 = row0 - bnw0 * 49;
        int row1 = row0 + 8;
        int bnw1 = row1 / 49, tk1 = row1 - bnw1 * 49;
#pragma unroll
        for (int nf = 0; nf < 4; nf++) {
            int ncol = (n0 + wn + nf * 8 + 2 * t) & 255;
            int head = ncol >> 5, dhw = (ncol & 31) >> 1;
            dst[(size_t)((bnw0 * 8 + head) * 49 + tk0) * 16 + dhw] =
                pack2(acc[mf][nf][0], acc[mf][nf][1]);
            dst[(size_t)((bnw1 * 8 + head) * 49 + tk1) * 16 + dhw] =
                pack2(acc[mf][nf][2], acc[mf][nf][3]);
        }
    }
}

// ---------------- kernel 4: attention (fp16 MMA) ----------------
__global__ __launch_bounds__(128, 9) void attn_f16(float* __restrict__ dout) {
    __shared__ unsigned SB[2400];
    __shared__ unsigned Vt[1152];
    unsigned* Qs = SB;
    unsigned* Ks = SB + 1280;
    unsigned* Ps = SB;

    int bn = blockIdx.x >> 3, h = blockIdx.x & 7, n = bn & 63;
    int tid = threadIdx.x, lane = tid & 31, w = tid >> 5;
    int g = lane >> 2, t = lane & 3;

    const unsigned* qw = g_qkv + (size_t)((bn * 8 + h) * 49) * 16;
    const unsigned* kw_ = qw + QSW;
    const unsigned* vw = qw + (size_t)2 * QSW;

    for (int i = tid; i < 1592; i += 128) {
        if (i < 300) Qs[980 + i] = 0;
        else if (i < 440) Ks[980 + (i - 300)] = 0;
        else Vt[i - 440] = 0;
    }
    __syncthreads();
    for (int i = tid; i < 784; i += 128) {
        int tk = i >> 4, kwi = i & 15;
        Qs[tk * 20 + kwi] = qw[i];
        Ks[tk * 20 + kwi] = kw_[i];
    }
    for (int i = tid; i < 400; i += 128) {
        int m = i >> 4, dw = i & 15;
        unsigned v0 = vw[(2 * m) * 16 + dw];
        unsigned v1 = (2 * m + 1 < 49) ? vw[(2 * m + 1) * 16 + dw] : 0u;
        __half2 va = *(__half2*)&v0, vb = *(__half2*)&v1;
        __half2 lo = __lows2half2(va, vb);
        __half2 hi = __highs2half2(va, vb);
        Vt[(2 * dw) * 36 + m] = *(unsigned*)&lo;
        Vt[(2 * dw + 1) * 36 + m] = *(unsigned*)&hi;
    }
    __syncthreads();

    float s[7][4];
#pragma unroll
    for (int nf = 0; nf < 7; nf++)
#pragma unroll
        for (int v = 0; v < 4; v++) s[nf][v] = 0.f;
#pragma unroll
    for (int st = 0; st < 2; st++) {
        unsigned a[4];
        int base = (w * 16 + g) * 20 + st * 8 + t;
        a[0] = Qs[base]; a[1] = Qs[base + 8 * 20];
        a[2] = Qs[base + 4]; a[3] = Qs[base + 8 * 20 + 4];
#pragma unroll
        for (int nf = 0; nf < 7; nf++) {
            unsigned b[2];
            int bb = (nf * 8 + g) * 20 + st * 8 + t;
            b[0] = Ks[bb]; b[1] = Ks[bb + 4];
            mma_f16(s[nf], a, b);
        }
    }

    const float scale = 0.17677669529663687f;
    const float* mk = g_mask + n * 2401;
    int row0 = w * 16 + g, row1 = row0 + 8;
#pragma unroll
    for (int nf = 0; nf < 7; nf++) {
        int c0 = nf * 8 + 2 * t, c1 = c0 + 1;
        float m00 = (c0 < 49) ? ((row0 < 49) ? __ldg(mk + row0 * 49 + c0) : 0.f) : NEG_INF;
        float m01 = (c1 < 49) ? ((row0 < 49) ? __ldg(mk + row0 * 49 + c1) : 0.f) : NEG_INF;
        float m10 = (c0 < 49) ? ((row1 < 49) ? __ldg(mk + row1 * 49 + c0) : 0.f) : NEG_INF;
        float m11 = (c1 < 49) ? ((row1 < 49) ? __ldg(mk + row1 * 49 + c1) : 0.f) : NEG_INF;
        s[nf][0] = s[nf][0] * scale + m00;
        s[nf][1] = s[nf][1] * scale + m01;
        s[nf][2] = s[nf][2] * scale + m10;
        s[nf][3] = s[nf][3] * scale + m11;
    }

    float mx0 = NEG_INF, mx1 = NEG_INF;
#pragma unroll
    for (int nf = 0; nf < 7; nf++) {
        mx0 = fmaxf(mx0, fmaxf(s[nf][0], s[nf][1]));
        mx1 = fmaxf(mx1, fmaxf(s[nf][2], s[nf][3]));
    }
    mx0 = fmaxf(mx0, __shfl_xor_sync(0xffffffffu, mx0, 1));
    mx0 = fmaxf(mx0, __shfl_xor_sync(0xffffffffu, mx0, 2));
    mx1 = fmaxf(mx1, __shfl_xor_sync(0xffffffffu, mx1, 1));
    mx1 = fmaxf(mx1, __shfl_xor_sync(0xffffffffu, mx1, 2));
    float sm0 = 0.f, sm1 = 0.f;
#pragma unroll
    for (int nf = 0; nf < 7; nf++) {
        s[nf][0] = __expf(s[nf][0] - mx0);
        s[nf][1] = __expf(s[nf][1] - mx0);
        s[nf][2] = __expf(s[nf][2] - mx1);
        s[nf][3] = __expf(s[nf][3] - mx1);
        sm0 += s[nf][0] + s[nf][1];
        sm1 += s[nf][2] + s[nf][3];
    }
    sm0 += __shfl_xor_sync(0xffffffffu, sm0, 1);
    sm0 += __shfl_xor_sync(0xffffffffu, sm0, 2);
    sm1 += __shfl_xor_sync(0xffffffffu, sm1, 1);
    sm1 += __shfl_xor_sync(0xffffffffu, sm1, 2);
    float inv0 = 1.f / sm0, inv1 = 1.f / sm1;
#pragma unroll
    for (int nf = 0; nf < 7; nf++) {
        s[nf][0] *= inv0; s[nf][1] *= inv0;
        s[nf][2] *= inv1; s[nf][3] *= inv1;
    }

    __syncthreads();

    float* ao = dout + (size_t)OUT_ELEMS + (size_t)((bn * 8 + h) * 49) * 49;
#pragma unroll
    for (int nf = 0; nf < 7; nf++) {
        int c0 = nf * 8 + 2 * t;
        if (row0 < 49) {
            if (c0 < 49) ao[row0 * 49 + c0] = s[nf][0];
            if (c0 + 1 < 49) ao[row0 * 49 + c0 + 1] = s[nf][1];
        }
        if (row1 < 49) {
            if (c0 < 49) ao[row1 * 49 + c0] = s[nf][2];
            if (c0 + 1 < 49) ao[row1 * 49 + c0 + 1] = s[nf][3];
        }
        Ps[row0 * 36 + nf * 4 + t] = pack2(s[nf][0], s[nf][1]);
        Ps[row1 * 36 + nf * 4 + t] = pack2(s[nf][2], s[nf][3]);
    }
    for (int i = tid; i < 256; i += 128)
        Ps[(i >> 2) * 36 + 28 + (i & 3)] = 0;
    __syncthreads();

    float o[4][4];
#pragma unroll
    for (int nf = 0; nf < 4; nf++)
#pragma unroll
        for (int v = 0; v < 4; v++) o[nf][v] = 0.f;
#pragma unroll
    for (int st = 0; st < 4; st++) {
        unsigned a[4];
        int base = (w * 16 + g) * 36 + st * 8 + t;
        a[0] = Ps[base]; a[1] = Ps[base + 8 * 36];
        a[2] = Ps[base + 4]; a[3] = Ps[base + 8 * 36 + 4];
#pragma unroll
        for (int nf = 0; nf < 4; nf++) {
            unsigned b[2];
            int bb = (nf * 8 + g) * 36 + st * 8 + t;
            b[0] = Vt[bb]; b[1] = Vt[bb + 4];
            mma_f16(o[nf], a, b);
        }
    }
    unsigned* ow = g_oattn;
#pragma unroll
    for (int nf = 0; nf < 4; nf++) {
        int cw = h * 16 + nf * 4 + t;
        if (row0 < 49)
            ow[(size_t)(bn * 49 + row0) * 128 + cw] = pack2(o[nf][0], o[nf][1]);
        if (row1 < 49)
            ow[(size_t)(bn * 49 + row1) * 128 + cw] = pack2(o[nf][2], o[nf][3]);
    }
}

// ---------------- kernel 5: output GEMM + bias (cp.async) ----------------
__global__ __launch_bounds__(256, 4) void gemm_out_f16(const float* __restrict__ bout) {
    __shared__ __align__(16) unsigned As[3][128 * 12];
    __shared__ __align__(16) unsigned Bs[3][64 * 12];
    int m0 = blockIdx.y * 128;
    int n0 = blockIdx.x * 64;
    int tid = threadIdx.x;
    int lane = tid & 31, wid = tid >> 5;
    int g = lane >> 2, t = lane & 3;
    int wm = (wid & 3) * 32, wn = (wid >> 2) * 32;

    float acc[2][4][4];
#pragma unroll
    for (int mf = 0; mf < 2; mf++)
#pragma unroll
        for (int nf = 0; nf < 4; nf++)
#pragma unroll
            for (int v = 0; v < 4; v++) acc[mf][nf][v] = 0.f;

    int arow = tid >> 1, apart = tid & 1;
    const unsigned* Ag = g_oattn + (size_t)(m0 + arow) * 128 + apart * 4;
    unsigned aDst0 = (unsigned)__cvta_generic_to_shared(&As[0][arow * 12 + apart * 4]);
    const unsigned* Bg = h_wout + (size_t)(n0 + (tid >> 1)) * 128 + apart * 4;
    unsigned bDst0 = (unsigned)__cvta_generic_to_shared(&Bs[0][(tid >> 1) * 12 + apart * 4]);
    const unsigned ASTG = 128 * 12 * 4, BSTG = 64 * 12 * 4;

    auto issue = [&](int s, int buf) {
        cpa16(aDst0 + buf * ASTG, Ag + s * 8);
        if (tid < 128) cpa16(bDst0 + buf * BSTG, Bg + s * 8);
        CP_COMMIT();
    };

    issue(0, 0);
    issue(1, 1);
    for (int s = 0; s < 16; s++) {
        int buf = s % 3;
        if (s == 15) CP_WAIT0(); else CP_WAIT1();   // tail fix
        __syncthreads();
        if (s + 2 < 16) issue(s + 2, (s + 2) % 3);
        unsigned a[2][4], b[4][2];
#pragma unroll
        for (int mf = 0; mf < 2; mf++) {
            int base = (wm + mf * 16 + g) * 12 + t;
            a[mf][0] = As[buf][base];
            a[mf][1] = As[buf][base + 8 * 12];
            a[mf][2] = As[buf][base + 4];
            a[mf][3] = As[buf][base + 8 * 12 + 4];
        }
#pragma unroll
        for (int nf = 0; nf < 4; nf++) {
            int bb = (wn + nf * 8 + g) * 12 + t;
            b[nf][0] = Bs[buf][bb];
            b[nf][1] = Bs[buf][bb + 4];
        }
#pragma unroll
        for (int mf = 0; mf < 2; mf++)
#pragma unroll
            for (int nf = 0; nf < 4; nf++)
                mma_f16(acc[mf][nf], a[mf], b[nf]);
        __syncthreads();
    }

#pragma unroll
    for (int mf = 0; mf < 2; mf++) {
        int row0 = m0 + wm + mf * 16 + g;
#pragma unroll
        for (int nf = 0; nf < 4; nf++) {
            int ncol = n0 + wn + nf * 8 + 2 * t;
            float2 bv = *(const float2*)&bout[ncol];
            *(float2*)&g_otok[(size_t)row0 * 256 + ncol] =
                make_float2(acc[mf][nf][0] + bv.x, acc[mf][nf][1] + bv.y);
            *(float2*)&g_otok[(size_t)(row0 + 8) * 256 + ncol] =
                make_float2(acc[mf][nf][2] + bv.x, acc[mf][nf][3] + bv.y);
        }
    }
}

// ---------------- kernel 6: scatter ----------------
__global__ void scatter_kernel(float* __restrict__ out) {
    __shared__ float s[32 * 57];
    int xsrow = blockIdx.x;
    int c0 = blockIdx.y * 32;
    int b = blockIdx.z;
    int wi = xsrow / 7, pi = xsrow - wi * 7;
    for (int j = threadIdx.x; j < 32 * 56; j += blockDim.x) {
        int cw = j & 31, pos = j >> 5;
        int wj = pos / 7, pj = pos - wj * 7;
        int col = pos + 3; if (col >= 56) col -= 56;
        int token = (b * 64 + wi * 8 + wj) * 49 + pi * 7 + pj;
        s[cw * 57 + col] = g_otok[(size_t)token * 256 + c0 + cw];
    }
    __syncthreads();
    int r = xsrow + 3; if (r >= 56) r -= 56;
    float* ob = out + ((size_t)(b * 256 + c0) * 3136) + r * 56;
    for (int i = threadIdx.x; i < 32 * 56; i += blockDim.x) {
        int c = i / 56, col = i - c * 56;
        ob[(size_t)c * 3136 + col] = s[c * 57 + col];
    }
}

// ---------------- launch ----------------
extern "C" void kernel_launch(void* const* d_in, const int* in_sizes, int n_in,
                              void* d_out, int out_size) {
    const float* x    = (const float*)d_in[0];
    const float* pe   = (const float*)d_in[1];
    const float* wqkv = (const float*)d_in[2];
    const float* wout = (const float*)d_in[3];
    const float* bout = (const float*)d_in[4];
    float* out = (float*)d_out;

    gather_kernel<<<dim3(56, 8, 32), 256>>>(x);
    convert_w<<<384, 256>>>(wqkv, wout);
    mask_kernel<<<64, 256>>>(pe);
    gemm_qkv_f16<<<dim3(12, 784), 256>>>();
    attn_f16<<<BNW * 8, 128>>>(out);
    gemm_out_f16<<<dim3(4, 784), 256>>>(bout);
    scatter_kernel<<<dim3(56, 8, 32), 256>>>(out);
}

// round 15
// speedup vs baseline: 2.2043x; 1.1118x over previous
#include <cuda_runtime.h>
#include <cuda_fp16.h>
#include <cstdint>

// ---------------- problem constants ----------------
#define B_      32
#define PP      49
#define NW      64
#define BNW     2048
#define MTOK    100352                 // BNW*49
#define QS      25690112               // halves per q/k/v tensor
#define QSW     (QS/2)                 // words per q/k/v tensor
#define OUT_ELEMS 25690112

#define NEG_INF __int_as_float(0xff800000)

// ---------------- scratch (half2-packed words) ----------------
__device__ __align__(16) unsigned g_xw[(size_t)MTOK * 128];     // [token][kw]
__device__ __align__(16) unsigned g_qkv[(size_t)3 * QSW];       // q|k|v, [bn,h,t][dhw]
__device__ __align__(16) unsigned g_oattn[(size_t)MTOK * 128];  // [token][kw]
__device__ __align__(16) unsigned h_wqkv[768 * 128];            // [n][kw]
__device__ __align__(16) unsigned h_wout[256 * 128];            // [n][kw]
__device__ float g_otok[(size_t)MTOK * 256];
__device__ float g_mask[NW * PP * PP];

// ---------------- helpers ----------------
__device__ __forceinline__ unsigned pack2(float a, float b) {
    __half2 h = __floats2half2_rn(a, b);
    return *(unsigned*)&h;
}
__device__ __forceinline__ void mma_f16(float* c, const unsigned* a, const unsigned* b) {
    asm volatile("mma.sync.aligned.m16n8k16.row.col.f32.f16.f16.f32 "
        "{%0,%1,%2,%3}, {%4,%5,%6,%7}, {%8,%9}, {%0,%1,%2,%3};"
        : "+f"(c[0]), "+f"(c[1]), "+f"(c[2]), "+f"(c[3])
        : "r"(a[0]), "r"(a[1]), "r"(a[2]), "r"(a[3]), "r"(b[0]), "r"(b[1]));
}
__device__ __forceinline__ void ldsm4(unsigned& d0, unsigned& d1, unsigned& d2, unsigned& d3,
                                      unsigned addr) {
    asm volatile("ldmatrix.sync.aligned.m8n8.x4.shared.b16 {%0,%1,%2,%3}, [%4];"
        : "=r"(d0), "=r"(d1), "=r"(d2), "=r"(d3) : "r"(addr));
}
__device__ __forceinline__ void ldsm2(unsigned& d0, unsigned& d1, unsigned addr) {
    asm volatile("ldmatrix.sync.aligned.m8n8.x2.shared.b16 {%0,%1}, [%2];"
        : "=r"(d0), "=r"(d1) : "r"(addr));
}
__device__ __forceinline__ void cpa16(unsigned saddr, const void* g) {
    asm volatile("cp.async.cg.shared.global [%0], [%1], 16;" :: "r"(saddr), "l"(g) : "memory");
}
#define CP_COMMIT() asm volatile("cp.async.commit_group;" ::: "memory")
#define CP_WAIT1()  asm volatile("cp.async.wait_group 1;" ::: "memory")
#define CP_WAIT0()  asm volatile("cp.async.wait_group 0;" ::: "memory")

// ---------------- kernel 1: gather + roll(-3) + window permute (half2 out) ----------------
__global__ void gather_kernel(const float* __restrict__ x) {
    __shared__ float s[32 * 57];
    int xsrow = blockIdx.x;
    int c0 = blockIdx.y * 32;
    int b = blockIdx.z;
    int r = xsrow + 3; if (r >= 56) r -= 56;
    const float* xb = x + ((size_t)(b * 256 + c0) * 3136) + r * 56;
    for (int i = threadIdx.x; i < 32 * 56; i += blockDim.x) {
        int c = i / 56, col = i - c * 56;
        s[c * 57 + col] = xb[(size_t)c * 3136 + col];
    }
    __syncthreads();
    int wi = xsrow / 7, pi = xsrow - wi * 7;
    for (int j = threadIdx.x; j < 16 * 56; j += blockDim.x) {
        int cp = j & 15, pos = j >> 4;
        int wj = pos / 7, pj = pos - wj * 7;
        int col = pos + 3; if (col >= 56) col -= 56;
        int token = (b * 64 + wi * 8 + wj) * 49 + pi * 7 + pj;
        g_xw[(size_t)token * 128 + (c0 >> 1) + cp] =
            pack2(s[(2 * cp) * 57 + col], s[(2 * cp + 1) * 57 + col]);
    }
}

// ---------------- kernel 1b: pre-pack weights to half2 [n][kw] ----------------
__global__ void convert_w(const float* __restrict__ wqkv, const float* __restrict__ wout) {
    int i = blockIdx.x * 256 + threadIdx.x;
    if (i < 768 * 128) {
        int n = i >> 7, kw = i & 127;
        h_wqkv[i] = pack2(wqkv[(size_t)(2 * kw) * 768 + n], wqkv[(size_t)(2 * kw + 1) * 768 + n]);
    }
    if (i < 256 * 128) {
        int n = i >> 7, kw = i & 127;
        h_wout[i] = pack2(wout[(size_t)(2 * kw) * 256 + n], wout[(size_t)(2 * kw + 1) * 256 + n]);
    }
}

// ---------------- kernel 2: mask ----------------
__global__ void mask_kernel(const float* __restrict__ pe) {
    int n = blockIdx.x;
    for (int e = threadIdx.x; e < 2401; e += blockDim.x) {
        int i = e / 49, j = e - i * 49;
        int i7 = i % 7, j7 = j % 7;
        int r0 = j / 7 - i / 7 + 6;
        int r1 = j7 - i7 + 6;
        float v = pe[r0 * 13 + r1];
        if (n >= 56 && ((i >= 28) != (j >= 28))) v = NEG_INF;
        if ((n == 55 || n == 63) && ((i7 >= 4) != (j7 >= 4))) v = NEG_INF;
        g_mask[n * 2401 + e] = v;
    }
}

// ========== fp16 GEMM, cp.async 3-stage, BK=32 halves (16 words), ldmatrix frags ==========
// smem row stride 20 words; 8 chunks; 8 warps 4m x 2n (warp tile 32x32).

// ---------------- kernel 3: QKV GEMM ----------------
__global__ __launch_bounds__(256, 4) void gemm_qkv_f16() {
    __shared__ __align__(16) unsigned As[3][128 * 20];
    __shared__ __align__(16) unsigned Bs[3][64 * 20];
    int m0 = blockIdx.y * 128;
    int n0 = blockIdx.x * 64;
    int tid = threadIdx.x;
    int lane = tid & 31, wid = tid >> 5;
    int g = lane >> 2, t = lane & 3;
    int wm = (wid & 3) * 32, wn = (wid >> 2) * 32;

    float acc[2][4][4];
#pragma unroll
    for (int mf = 0; mf < 2; mf++)
#pragma unroll
        for (int nf = 0; nf < 4; nf++)
#pragma unroll
            for (int v = 0; v < 4; v++) acc[mf][nf][v] = 0.f;

    // staging: A 128 rows x 16 words (2 cpa16/thread), B 64 rows x 16 words (1 cpa16/thread)
    int arow = tid >> 1, aseg = (tid & 1) * 8;
    int brow = tid >> 2, bseg = (tid & 3) * 4;
    const unsigned* Ag = g_xw + (size_t)(m0 + arow) * 128 + aseg;
    const unsigned* Bg = h_wqkv + (size_t)(n0 + brow) * 128 + bseg;
    unsigned aDst = (unsigned)__cvta_generic_to_shared(&As[0][arow * 20 + aseg]);
    unsigned bDst = (unsigned)__cvta_generic_to_shared(&Bs[0][brow * 20 + bseg]);
    const unsigned ASTG = 128 * 20 * 4, BSTG = 64 * 20 * 4;

    auto issue = [&](int s, int buf) {
        cpa16(aDst + buf * ASTG, Ag + s * 16);
        cpa16(aDst + buf * ASTG + 16, Ag + s * 16 + 4);
        cpa16(bDst + buf * BSTG, Bg + s * 16);
        CP_COMMIT();
    };

    // ldmatrix lane addressing (word offsets; +kf*8 at use)
    unsigned aBase = (unsigned)__cvta_generic_to_shared(&As[0][0]);
    unsigned bBase = (unsigned)__cvta_generic_to_shared(&Bs[0][0]);
    int rowsel = lane & 15, segsel = lane >> 4;
    int aoff0 = (wm + rowsel) * 20 + segsel * 4;          // mf=0 (rows wm..wm+15)
    int aoff1 = (wm + 16 + rowsel) * 20 + segsel * 4;     // mf=1
    int bcol = (lane & 7) + ((lane >> 4) & 1) * 8;
    int bwrd = ((lane >> 3) & 1) * 4;
    int boff0 = (wn + bcol) * 20 + bwrd;                  // nf pair 0 (cols wn..wn+15)
    int boff1 = (wn + 16 + bcol) * 20 + bwrd;             // nf pair 1

    issue(0, 0);
    issue(1, 1);
    for (int s = 0; s < 8; s++) {
        int buf = s % 3;
        if (s == 7) CP_WAIT0(); else CP_WAIT1();
        __syncthreads();
        if (s + 2 < 8) issue(s + 2, (s + 2) % 3);
        unsigned aB = aBase + buf * ASTG, bB = bBase + buf * BSTG;
#pragma unroll
        for (int kf = 0; kf < 2; kf++) {
            unsigned a[2][4], b[4][2];
            ldsm4(a[0][0], a[0][1], a[0][2], a[0][3], aB + (aoff0 + kf * 8) * 4);
            ldsm4(a[1][0], a[1][1], a[1][2], a[1][3], aB + (aoff1 + kf * 8) * 4);
            ldsm4(b[0][0], b[0][1], b[1][0], b[1][1], bB + (boff0 + kf * 8) * 4);
            ldsm4(b[2][0], b[2][1], b[3][0], b[3][1], bB + (boff1 + kf * 8) * 4);
#pragma unroll
            for (int mf = 0; mf < 2; mf++)
#pragma unroll
                for (int nf = 0; nf < 4; nf++)
                    mma_f16(acc[mf][nf], a[mf], b[nf]);
        }
    }

    int mat = n0 >> 8;
    unsigned* dst = g_qkv + (size_t)mat * QSW;
#pragma unroll
    for (int mf = 0; mf < 2; mf++) {
        int row0 = m0 + wm + mf * 16 + g;
        int bnw0 = row0 / 49, tk0 = row0 - bnw0 * 49;
        int row1 = row0 + 8;
        int bnw1 = row1 / 49, tk1 = row1 - bnw1 * 49;
#pragma unroll
        for (int nf = 0; nf < 4; nf++) {
            int ncol = (n0 + wn + nf * 8 + 2 * t) & 255;
            int head = ncol >> 5, dhw = (ncol & 31) >> 1;
            dst[(size_t)((bnw0 * 8 + head) * 49 + tk0) * 16 + dhw] =
                pack2(acc[mf][nf][0], acc[mf][nf][1]);
            dst[(size_t)((bnw1 * 8 + head) * 49 + tk1) * 16 + dhw] =
                pack2(acc[mf][nf][2], acc[mf][nf][3]);
        }
    }
}

// ---------------- kernel 4: attention (fp16 MMA, ldmatrix frags) ----------------
__global__ __launch_bounds__(128, 9) void attn_f16(float* __restrict__ dout) {
    __shared__ unsigned SB[2400];
    __shared__ unsigned Vt[1152];
    unsigned* Qs = SB;
    unsigned* Ks = SB + 1280;
    unsigned* Ps = SB;

    int bn = blockIdx.x >> 3, h = blockIdx.x & 7, n = bn & 63;
    int tid = threadIdx.x, lane = tid & 31, w = tid >> 5;
    int g = lane >> 2, t = lane & 3;
    int rowsel = lane & 15, segsel = lane >> 4;
    int bcol = (lane & 7) + ((lane >> 4) & 1) * 8;
    int bwrd = ((lane >> 3) & 1) * 4;

    const unsigned* qw = g_qkv + (size_t)((bn * 8 + h) * 49) * 16;
    const unsigned* kw_ = qw + QSW;
    const unsigned* vw = qw + (size_t)2 * QSW;

    for (int i = tid; i < 1592; i += 128) {
        if (i < 300) Qs[980 + i] = 0;
        else if (i < 440) Ks[980 + (i - 300)] = 0;
        else Vt[i - 440] = 0;
    }
    __syncthreads();
    for (int i = tid; i < 784; i += 128) {
        int tk = i >> 4, kwi = i & 15;
        Qs[tk * 20 + kwi] = qw[i];
        Ks[tk * 20 + kwi] = kw_[i];
    }
    for (int i = tid; i < 400; i += 128) {
        int m = i >> 4, dw = i & 15;
        unsigned v0 = vw[(2 * m) * 16 + dw];
        unsigned v1 = (2 * m + 1 < 49) ? vw[(2 * m + 1) * 16 + dw] : 0u;
        __half2 va = *(__half2*)&v0, vb = *(__half2*)&v1;
        __half2 lo = __lows2half2(va, vb);
        __half2 hi = __highs2half2(va, vb);
        Vt[(2 * dw) * 36 + m] = *(unsigned*)&lo;
        Vt[(2 * dw + 1) * 36 + m] = *(unsigned*)&hi;
    }
    __syncthreads();

    unsigned qBase = (unsigned)__cvta_generic_to_shared(Qs);
    unsigned kBase = (unsigned)__cvta_generic_to_shared(Ks);
    unsigned vBase = (unsigned)__cvta_generic_to_shared(Vt);

    // S = Q @ K^T  (2 k16 steps over dh=32)
    float s[7][4];
#pragma unroll
    for (int nf = 0; nf < 7; nf++)
#pragma unroll
        for (int v = 0; v < 4; v++) s[nf][v] = 0.f;
#pragma unroll
    for (int st = 0; st < 2; st++) {
        unsigned a[4], b[7][2];
        ldsm4(a[0], a[1], a[2], a[3],
              qBase + ((w * 16 + rowsel) * 20 + st * 8 + segsel * 4) * 4);
        ldsm4(b[0][0], b[0][1], b[1][0], b[1][1],
              kBase + ((bcol) * 20 + st * 8 + bwrd) * 4);
        ldsm4(b[2][0], b[2][1], b[3][0], b[3][1],
              kBase + ((16 + bcol) * 20 + st * 8 + bwrd) * 4);
        ldsm4(b[4][0], b[4][1], b[5][0], b[5][1],
              kBase + ((32 + bcol) * 20 + st * 8 + bwrd) * 4);
        ldsm2(b[6][0], b[6][1],
              kBase + ((48 + (lane & 7)) * 20 + st * 8 + ((lane >> 3) & 3) * 4) * 4);
#pragma unroll
        for (int nf = 0; nf < 7; nf++)
            mma_f16(s[nf], a, b[nf]);
    }

    const float scale = 0.17677669529663687f;
    const float* mk = g_mask + n * 2401;
    int row0 = w * 16 + g, row1 = row0 + 8;
#pragma unroll
    for (int nf = 0; nf < 7; nf++) {
        int c0 = nf * 8 + 2 * t, c1 = c0 + 1;
        float m00 = (c0 < 49) ? ((row0 < 49) ? __ldg(mk + row0 * 49 + c0) : 0.f) : NEG_INF;
        float m01 = (c1 < 49) ? ((row0 < 49) ? __ldg(mk + row0 * 49 + c1) : 0.f) : NEG_INF;
        float m10 = (c0 < 49) ? ((row1 < 49) ? __ldg(mk + row1 * 49 + c0) : 0.f) : NEG_INF;
        float m11 = (c1 < 49) ? ((row1 < 49) ? __ldg(mk + row1 * 49 + c1) : 0.f) : NEG_INF;
        s[nf][0] = s[nf][0] * scale + m00;
        s[nf][1] = s[nf][1] * scale + m01;
        s[nf][2] = s[nf][2] * scale + m10;
        s[nf][3] = s[nf][3] * scale + m11;
    }

    float mx0 = NEG_INF, mx1 = NEG_INF;
#pragma unroll
    for (int nf = 0; nf < 7; nf++) {
        mx0 = fmaxf(mx0, fmaxf(s[nf][0], s[nf][1]));
        mx1 = fmaxf(mx1, fmaxf(s[nf][2], s[nf][3]));
    }
    mx0 = fmaxf(mx0, __shfl_xor_sync(0xffffffffu, mx0, 1));
    mx0 = fmaxf(mx0, __shfl_xor_sync(0xffffffffu, mx0, 2));
    mx1 = fmaxf(mx1, __shfl_xor_sync(0xffffffffu, mx1, 1));
    mx1 = fmaxf(mx1, __shfl_xor_sync(0xffffffffu, mx1, 2));
    float sm0 = 0.f, sm1 = 0.f;
#pragma unroll
    for (int nf = 0; nf < 7; nf++) {
        s[nf][0] = __expf(s[nf][0] - mx0);
        s[nf][1] = __expf(s[nf][1] - mx0);
        s[nf][2] = __expf(s[nf][2] - mx1);
        s[nf][3] = __expf(s[nf][3] - mx1);
        sm0 += s[nf][0] + s[nf][1];
        sm1 += s[nf][2] + s[nf][3];
    }
    sm0 += __shfl_xor_sync(0xffffffffu, sm0, 1);
    sm0 += __shfl_xor_sync(0xffffffffu, sm0, 2);
    sm1 += __shfl_xor_sync(0xffffffffu, sm1, 1);
    sm1 += __shfl_xor_sync(0xffffffffu, sm1, 2);
    float inv0 = 1.f / sm0, inv1 = 1.f / sm1;
#pragma unroll
    for (int nf = 0; nf < 7; nf++) {
        s[nf][0] *= inv0; s[nf][1] *= inv0;
        s[nf][2] *= inv1; s[nf][3] *= inv1;
    }

    __syncthreads();

    float* ao = dout + (size_t)OUT_ELEMS + (size_t)((bn * 8 + h) * 49) * 49;
#pragma unroll
    for (int nf = 0; nf < 7; nf++) {
        int c0 = nf * 8 + 2 * t;
        if (row0 < 49) {
            if (c0 < 49) ao[row0 * 49 + c0] = s[nf][0];
            if (c0 + 1 < 49) ao[row0 * 49 + c0 + 1] = s[nf][1];
        }
        if (row1 < 49) {
            if (c0 < 49) ao[row1 * 49 + c0] = s[nf][2];
            if (c0 + 1 < 49) ao[row1 * 49 + c0 + 1] = s[nf][3];
        }
        Ps[row0 * 36 + nf * 4 + t] = pack2(s[nf][0], s[nf][1]);
        Ps[row1 * 36 + nf * 4 + t] = pack2(s[nf][2], s[nf][3]);
    }
    for (int i = tid; i < 256; i += 128)
        Ps[(i >> 2) * 36 + 28 + (i & 3)] = 0;
    __syncthreads();

    unsigned pBase = (unsigned)__cvta_generic_to_shared(Ps);

    float o[4][4];
#pragma unroll
    for (int nf = 0; nf < 4; nf++)
#pragma unroll
        for (int v = 0; v < 4; v++) o[nf][v] = 0.f;
#pragma unroll
    for (int st = 0; st < 4; st++) {
        unsigned a[4], b[4][2];
        ldsm4(a[0], a[1], a[2], a[3],
              pBase + ((w * 16 + rowsel) * 36 + st * 8 + segsel * 4) * 4);
        ldsm4(b[0][0], b[0][1], b[1][0], b[1][1],
              vBase + ((bcol) * 36 + st * 8 + bwrd) * 4);
        ldsm4(b[2][0], b[2][1], b[3][0], b[3][1],
              vBase + ((16 + bcol) * 36 + st * 8 + bwrd) * 4);
#pragma unroll
        for (int nf = 0; nf < 4; nf++)
            mma_f16(o[nf], a, b[nf]);
    }
    unsigned* ow = g_oattn;
#pragma unroll
    for (int nf = 0; nf < 4; nf++) {
        int cw = h * 16 + nf * 4 + t;
        if (row0 < 49)
            ow[(size_t)(bn * 49 + row0) * 128 + cw] = pack2(o[nf][0], o[nf][1]);
        if (row1 < 49)
            ow[(size_t)(bn * 49 + row1) * 128 + cw] = pack2(o[nf][2], o[nf][3]);
    }
}

// ---------------- kernel 5: output GEMM + bias (cp.async, ldmatrix) ----------------
__global__ __launch_bounds__(256, 4) void gemm_out_f16(const float* __restrict__ bout) {
    __shared__ __align__(16) unsigned As[3][128 * 20];
    __shared__ __align__(16) unsigned Bs[3][64 * 20];
    int m0 = blockIdx.y * 128;
    int n0 = blockIdx.x * 64;
    int tid = threadIdx.x;
    int lane = tid & 31, wid = tid >> 5;
    int g = lane >> 2, t = lane & 3;
    int wm = (wid & 3) * 32, wn = (wid >> 2) * 32;

    float acc[2][4][4];
#pragma unroll
    for (int mf = 0; mf < 2; mf++)
#pragma unroll
        for (int nf = 0; nf < 4; nf++)
#pragma unroll
            for (int v = 0; v < 4; v++) acc[mf][nf][v] = 0.f;

    int arow = tid >> 1, aseg = (tid & 1) * 8;
    int brow = tid >> 2, bseg = (tid & 3) * 4;
    const unsigned* Ag = g_oattn + (size_t)(m0 + arow) * 128 + aseg;
    const unsigned* Bg = h_wout + (size_t)(n0 + brow) * 128 + bseg;
    unsigned aDst = (unsigned)__cvta_generic_to_shared(&As[0][arow * 20 + aseg]);
    unsigned bDst = (unsigned)__cvta_generic_to_shared(&Bs[0][brow * 20 + bseg]);
    const unsigned ASTG = 128 * 20 * 4, BSTG = 64 * 20 * 4;

    auto issue = [&](int s, int buf) {
        cpa16(aDst + buf * ASTG, Ag + s * 16);
        cpa16(aDst + buf * ASTG + 16, Ag + s * 16 + 4);
        cpa16(bDst + buf * BSTG, Bg + s * 16);
        CP_COMMIT();
    };

    unsigned aBase = (unsigned)__cvta_generic_to_shared(&As[0][0]);
    unsigned bBase = (unsigned)__cvta_generic_to_shared(&Bs[0][0]);
    int rowsel = lane & 15, segsel = lane >> 4;
    int aoff0 = (wm + rowsel) * 20 + segsel * 4;
    int aoff1 = (wm + 16 + rowsel) * 20 + segsel * 4;
    int bcol = (lane & 7) + ((lane >> 4) & 1) * 8;
    int bwrd = ((lane >> 3) & 1) * 4;
    int boff0 = (wn + bcol) * 20 + bwrd;
    int boff1 = (wn + 16 + bcol) * 20 + bwrd;

    issue(0, 0);
    issue(1, 1);
    for (int s = 0; s < 8; s++) {
        int buf = s % 3;
        if (s == 7) CP_WAIT0(); else CP_WAIT1();
        __syncthreads();
        if (s + 2 < 8) issue(s + 2, (s + 2) % 3);
        unsigned aB = aBase + buf * ASTG, bB = bBase + buf * BSTG;
#pragma unroll
        for (int kf = 0; kf < 2; kf++) {
            unsigned a[2][4], b[4][2];
            ldsm4(a[0][0], a[0][1], a[0][2], a[0][3], aB + (aoff0 + kf * 8) * 4);
            ldsm4(a[1][0], a[1][1], a[1][2], a[1][3], aB + (aoff1 + kf * 8) * 4);
            ldsm4(b[0][0], b[0][1], b[1][0], b[1][1], bB + (boff0 + kf * 8) * 4);
            ldsm4(b[2][0], b[2][1], b[3][0], b[3][1], bB + (boff1 + kf * 8) * 4);
#pragma unroll
            for (int mf = 0; mf < 2; mf++)
#pragma unroll
                for (int nf = 0; nf < 4; nf++)
                    mma_f16(acc[mf][nf], a[mf], b[nf]);
        }
    }

#pragma unroll
    for (int mf = 0; mf < 2; mf++) {
        int row0 = m0 + wm + mf * 16 + g;
#pragma unroll
        for (int nf = 0; nf < 4; nf++) {
            int ncol = n0 + wn + nf * 8 + 2 * t;
            float2 bv = *(const float2*)&bout[ncol];
            *(float2*)&g_otok[(size_t)row0 * 256 + ncol] =
                make_float2(acc[mf][nf][0] + bv.x, acc[mf][nf][1] + bv.y);
            *(float2*)&g_otok[(size_t)(row0 + 8) * 256 + ncol] =
                make_float2(acc[mf][nf][2] + bv.x, acc[mf][nf][3] + bv.y);
        }
    }
}

// ---------------- kernel 6: scatter ----------------
__global__ void scatter_kernel(float* __restrict__ out) {
    __shared__ float s[32 * 57];
    int xsrow = blockIdx.x;
    int c0 = blockIdx.y * 32;
    int b = blockIdx.z;
    int wi = xsrow / 7, pi = xsrow - wi * 7;
    for (int j = threadIdx.x; j < 32 * 56; j += blockDim.x) {
        int cw = j & 31, pos = j >> 5;
        int wj = pos / 7, pj = pos - wj * 7;
        int col = pos + 3; if (col >= 56) col -= 56;
        int token = (b * 64 + wi * 8 + wj) * 49 + pi * 7 + pj;
        s[cw * 57 + col] = g_otok[(size_t)token * 256 + c0 + cw];
    }
    __syncthreads();
    int r = xsrow + 3; if (r >= 56) r -= 56;
    float* ob = out + ((size_t)(b * 256 + c0) * 3136) + r * 56;
    for (int i = threadIdx.x; i < 32 * 56; i += blockDim.x) {
        int c = i / 56, col = i - c * 56;
        ob[(size_t)c * 3136 + col] = s[c * 57 + col];
    }
}

// ---------------- launch ----------------
extern "C" void kernel_launch(void* const* d_in, const int* in_sizes, int n_in,
                              void* d_out, int out_size) {
    const float* x    = (const float*)d_in[0];
    const float* pe   = (const float*)d_in[1];
    const float* wqkv = (const float*)d_in[2];
    const float* wout = (const float*)d_in[3];
    const float* bout = (const float*)d_in[4];
    float* out = (float*)d_out;

    gather_kernel<<<dim3(56, 8, 32), 256>>>(x);
    convert_w<<<384, 256>>>(wqkv, wout);
    mask_kernel<<<64, 256>>>(pe);
    gemm_qkv_f16<<<dim3(12, 784), 256>>>();
    attn_f16<<<BNW * 8, 128>>>(out);
    gemm_out_f16<<<dim3(4, 784), 256>>>(bout);
    scatter_kernel<<<dim3(56, 8, 32), 256>>>(out);
}